// round 6
// baseline (speedup 1.0000x reference)
#include <cuda_runtime.h>

#define T_STEPS 256
#define BATCH   64
#define IN_DIM  512
#define HID     1024
#define MDIM    2048
#define NB      128
#define NT      512
#define SKU     48      // upd split-K count (Kc = 64)

// ---------------- static device scratch ----------------
__device__ float g_xh[(size_t)T_STEPS * BATCH * HID];   // x@Wxh + bh (64 MB)
__device__ float g_h[BATCH * HID];                      // h_t
__device__ float g_c[BATCH * HID];                      // running c = m @ Wmh.T
__device__ float g_dm[BATCH * MDIM];                    // delta m (active cols)
__device__ float g_hpart[32 * BATCH * HID];             // h split-K partials
__device__ float g_upart[(size_t)SKU * BATCH * MDIM];   // upd split-K partials (24 MB)
__device__ unsigned g_cnt;
__device__ unsigned g_gen;

// ---------------- packed fp32x2 ----------------
__device__ __forceinline__ unsigned long long pack2(float a) {
    unsigned long long r;
    asm("mov.b64 %0, {%1, %1};" : "=l"(r) : "f"(a));
    return r;
}
__device__ __forceinline__ void ffma2(unsigned long long& c, unsigned long long a, unsigned long long b) {
    asm("fma.rn.f32x2 %0, %1, %2, %0;" : "+l"(c) : "l"(a), "l"(b));
}

// ---------------- grid barrier (NB blocks co-resident) ----------------
__device__ __forceinline__ void grid_barrier() {
    __threadfence();
    __syncthreads();
    if (threadIdx.x == 0) {
        volatile unsigned* vg = &g_gen;
        unsigned old = *vg;
        unsigned prev = atomicAdd(&g_cnt, 1u);
        if (prev == NB - 1) {
            atomicExch(&g_cnt, 0u);
            __threadfence();
            atomicAdd(&g_gen, 1u);
        } else {
            while (*vg == old) { __nanosleep(64); }
        }
    }
    __syncthreads();
}

// ---------------- 64x256 tile, 512 threads, 4x8 per thread ----------------
// As: [16][68] (As[k][row]); Bs: [16][260] (Bs[k][col])
__device__ __forceinline__ void tile_compute4(const float* As, const float* Bs,
                                              int ty, int tx, unsigned long long acc[4][4]) {
#pragma unroll
    for (int kk = 0; kk < 16; kk++) {
        float4 a0 = *(const float4*)(As + kk * 68 + ty * 4);
        const unsigned long long* bp = (const unsigned long long*)(Bs + kk * 260 + tx * 8);
        unsigned long long b0 = bp[0], b1 = bp[1], b2 = bp[2], b3 = bp[3];
        float a_s[4] = {a0.x, a0.y, a0.z, a0.w};
#pragma unroll
        for (int r = 0; r < 4; r++) {
            unsigned long long av = pack2(a_s[r]);
            ffma2(acc[r][0], av, b0);
            ffma2(acc[r][1], av, b1);
            ffma2(acc[r][2], av, b2);
            ffma2(acc[r][3], av, b3);
        }
    }
}

// ---------------- 64x256 tile, 256 threads, 8x8 per thread (prologue) -------
__device__ __forceinline__ void tile_compute8(const float* As, const float* Bs,
                                              int ty, int tx, unsigned long long acc[8][4]) {
#pragma unroll
    for (int kk = 0; kk < 16; kk++) {
        float4 a0 = *(const float4*)(As + kk * 68 + ty * 8);
        float4 a1 = *(const float4*)(As + kk * 68 + ty * 8 + 4);
        const unsigned long long* bp = (const unsigned long long*)(Bs + kk * 260 + tx * 8);
        unsigned long long b0 = bp[0], b1 = bp[1], b2 = bp[2], b3 = bp[3];
        float a_s[8] = {a0.x, a0.y, a0.z, a0.w, a1.x, a1.y, a1.z, a1.w};
#pragma unroll
        for (int r = 0; r < 8; r++) {
            unsigned long long av = pack2(a_s[r]);
            ffma2(acc[r][0], av, b0);
            ffma2(acc[r][1], av, b1);
            ffma2(acc[r][2], av, b2);
            ffma2(acc[r][3], av, b3);
        }
    }
}

// ---------------- prologue: g_xh = x @ Wxh + bh ----------------
__global__ __launch_bounds__(256) void xh_kernel(
    const float* __restrict__ X, const float* __restrict__ Wxh, const float* __restrict__ bh)
{
    __shared__ float As[16 * 68];
    __shared__ float Bs[16 * 260];
    const int tid = threadIdx.x;
    const int ty = tid >> 5, tx = tid & 31;
    const int colBase = blockIdx.x * 256;
    const int rowBase = blockIdx.y * 64;

    unsigned long long acc[8][4];
#pragma unroll
    for (int r = 0; r < 8; r++)
#pragma unroll
        for (int c = 0; c < 4; c++) acc[r][c] = 0ULL;

    for (int ch = 0; ch < 32; ch++) {
        int kb = ch << 4;
        {
            int row = tid >> 2, kl = (tid & 3) << 2;
            float4 v = *(const float4*)(X + (size_t)(rowBase + row) * IN_DIM + kb + kl);
            As[(kl + 0) * 68 + row] = v.x; As[(kl + 1) * 68 + row] = v.y;
            As[(kl + 2) * 68 + row] = v.z; As[(kl + 3) * 68 + row] = v.w;
        }
#pragma unroll
        for (int i = 0; i < 4; i++) {
            int g = tid + i * 256;
            int kl = g >> 6, col4 = (g & 63) << 2;
            float4 v = *(const float4*)(Wxh + (size_t)(kb + kl) * HID + colBase + col4);
            *(float4*)(Bs + kl * 260 + col4) = v;
        }
        __syncthreads();
        tile_compute8(As, Bs, ty, tx, acc);
        __syncthreads();
    }

#pragma unroll
    for (int r = 0; r < 8; r++) {
        int row = rowBase + ty * 8 + r;
        int jg = colBase + tx * 8;
#pragma unroll
        for (int c = 0; c < 4; c++) {
            float2 v = *(float2*)&acc[r][c];
            float2 bb = *(const float2*)(bh + jg + c * 2);
            v.x += bb.x; v.y += bb.y;
            *(float2*)(g_xh + (size_t)row * HID + jg + c * 2) = v;
        }
    }
}

// ---------------- persistent recurrence ----------------
__global__ __launch_bounds__(NT, 1) void rnn_persistent(
    const float* __restrict__ m_prev, const float* __restrict__ Wmh,
    const float* __restrict__ Wmm, const float* __restrict__ Whm,
    const float* __restrict__ bm, float* __restrict__ out)
{
    __shared__ float As[16 * 68];
    __shared__ float Bs[16 * 260];
    const int tid = threadIdx.x;
    const int ty = tid >> 5, tx = tid & 31;     // ty: 0..15 (4 rows each), tx: 0..31 (8 cols)
    const int bid = blockIdx.x;
    const int ft = bid * NT + tid;              // [0, 65536)

    for (int t = 0; t < T_STEPS; t++) {
        const float* mP = t ? (out + (size_t)(t - 1) * BATCH * MDIM) : m_prev;
        const int kcur = t ? min(__ffs(t), 8) : 8;
        const int kprev = (t <= 1) ? 8 : min(__ffs(t - 1), 8);
        const int nsplit = kprev * 4;                  // Kc = 64 ALWAYS (4 chunks of 16)
        const float* dsrc = t ? g_dm : m_prev;         // delta-m source

        // ---------- phase 1: c-increment partials = dm @ Wmh.T (K = kprev*256) ----------
        {
            const int units = nsplit * 4;              // 16..128, always <= NB
            if (bid < units) {
                const int s = bid % nsplit;
                const int ct = bid / nsplit;
                const int colBase = ct * 256;
                const int kBase0 = s * 64;
                unsigned long long acc[4][4];
#pragma unroll
                for (int r = 0; r < 4; r++)
#pragma unroll
                    for (int c = 0; c < 4; c++) acc[r][c] = 0ULL;

#pragma unroll
                for (int ch = 0; ch < 4; ch++) {
                    int kb = kBase0 + (ch << 4);
                    if (tid < 256) {
                        int row = tid >> 2, kl = (tid & 3) << 2;
                        float4 v = __ldcg((const float4*)(dsrc + (size_t)row * MDIM + kb + kl));
                        As[(kl + 0) * 68 + row] = v.x; As[(kl + 1) * 68 + row] = v.y;
                        As[(kl + 2) * 68 + row] = v.z; As[(kl + 3) * 68 + row] = v.w;
                    }
#pragma unroll
                    for (int i = 0; i < 2; i++) {
                        int g = tid + i * 512;
                        int col = g >> 2, kl = (g & 3) << 2;
                        float4 v = *(const float4*)(Wmh + (size_t)(colBase + col) * MDIM + kb + kl);
                        Bs[(kl + 0) * 260 + col] = v.x; Bs[(kl + 1) * 260 + col] = v.y;
                        Bs[(kl + 2) * 260 + col] = v.z; Bs[(kl + 3) * 260 + col] = v.w;
                    }
                    __syncthreads();
                    tile_compute4(As, Bs, ty, tx, acc);
                    __syncthreads();
                }
#pragma unroll
                for (int r = 0; r < 4; r++) {
                    int row = ty * 4 + r;
                    size_t base = (size_t)s * (BATCH * HID) + (size_t)row * HID + colBase + tx * 8;
#pragma unroll
                    for (int c = 0; c < 4; c++)
                        *(float2*)(g_hpart + base + c * 2) = *(float2*)&acc[r][c];
                }
            }
        }
        grid_barrier();

        // ---------- phase 2: c += sum partials; h = tanh(xh_t + c) ----------
        {
            float cv = (t == 0) ? 0.0f : g_c[ft];
            float s = 0.0f;
            for (int p = 0; p < nsplit; p++)
                s += __ldcg(g_hpart + (size_t)p * (BATCH * HID) + ft);
            cv += s;
            g_c[ft] = cv;
            g_h[ft] = tanhf(g_xh[(size_t)t * (BATCH * HID) + ft] + cv);
        }
        grid_barrier();

        // ---------- phase 3: upd partials ([m|h] @ [Wmm|Whm].T), K=3072, SKU splits ----------
        for (int u = bid; u < SKU * kcur; u += NB) {
            const int ct = u / SKU, s = u - ct * SKU;
            const int colBase = ct * 256;
            const int kBase0 = s * 64;
            unsigned long long acc[4][4];
#pragma unroll
            for (int r = 0; r < 4; r++)
#pragma unroll
                for (int c = 0; c < 4; c++) acc[r][c] = 0ULL;

#pragma unroll
            for (int ch = 0; ch < 4; ch++) {
                int kb = kBase0 + (ch << 4);
                if (tid < 256) {
                    int row = tid >> 2, kl = (tid & 3) << 2;
                    float4 v;
                    if (kb < MDIM) v = __ldcg((const float4*)(mP + (size_t)row * MDIM + kb + kl));
                    else           v = __ldcg((const float4*)(g_h + (size_t)row * HID + (kb - MDIM) + kl));
                    As[(kl + 0) * 68 + row] = v.x; As[(kl + 1) * 68 + row] = v.y;
                    As[(kl + 2) * 68 + row] = v.z; As[(kl + 3) * 68 + row] = v.w;
                }
#pragma unroll
                for (int i = 0; i < 2; i++) {
                    int g = tid + i * 512;
                    int col = g >> 2, kl = (g & 3) << 2;
                    int jg = colBase + col;
                    float4 v;
                    if (kb < MDIM) v = *(const float4*)(Wmm + (size_t)jg * MDIM + kb + kl);
                    else           v = *(const float4*)(Whm + (size_t)jg * HID + (kb - MDIM) + kl);
                    Bs[(kl + 0) * 260 + col] = v.x; Bs[(kl + 1) * 260 + col] = v.y;
                    Bs[(kl + 2) * 260 + col] = v.z; Bs[(kl + 3) * 260 + col] = v.w;
                }
                __syncthreads();
                tile_compute4(As, Bs, ty, tx, acc);
                __syncthreads();
            }
#pragma unroll
            for (int r = 0; r < 4; r++) {
                int row = ty * 4 + r;
                size_t base = (size_t)s * (BATCH * MDIM) + (size_t)row * MDIM + colBase + tx * 8;
#pragma unroll
                for (int c = 0; c < 4; c++)
                    *(float2*)(g_upart + base + c * 2) = *(float2*)&acc[r][c];
            }
        }
        grid_barrier();

        // ---------- phase 4: merge -> out[t], write delta-m ----------
        {
            const int b = ft >> 10;
            const int j = (ft & 1023) << 1;
            const int ac = kcur << 8;
            const float* mrow = mP + (size_t)b * MDIM;
            float2 v;
            if (j < ac) {
                v = *(const float2*)(bm + j);
#pragma unroll 8
                for (int p = 0; p < SKU; p++) {
                    float2 w = __ldcg((const float2*)(g_upart + (size_t)p * (BATCH * MDIM) + (size_t)b * MDIM + j));
                    v.x += w.x; v.y += w.y;
                }
                float2 mo = *(const float2*)(mrow + j);
                *(float2*)(g_dm + (size_t)b * MDIM + j) = make_float2(v.x - mo.x, v.y - mo.y);
            } else {
                v = *(const float2*)(mrow + j);
            }
            *(float2*)(out + (size_t)t * (BATCH * MDIM) + (size_t)b * MDIM + j) = v;
            if (t == T_STEPS - 1)
                *(float2*)(out + (size_t)T_STEPS * (BATCH * MDIM) + (size_t)b * MDIM + j) = v;
        }
        grid_barrier();
    }
}

// ---------------- host ----------------
extern "C" void kernel_launch(void* const* d_in, const int* in_sizes, int n_in,
                              void* d_out, int out_size)
{
    const float* x      = (const float*)d_in[0];
    const float* m_prev = (const float*)d_in[1];
    const float* Wxh    = (const float*)d_in[2];
    const float* Whm    = (const float*)d_in[3];
    const float* Wmm    = (const float*)d_in[4];
    const float* Wmh    = (const float*)d_in[5];
    const float* bm     = (const float*)d_in[6];
    const float* bh     = (const float*)d_in[7];
    float* out = (float*)d_out;
    (void)in_sizes; (void)n_in; (void)out_size;

    xh_kernel<<<dim3(4, 256), 256>>>(x, Wxh, bh);
    rnn_persistent<<<NB, NT>>>(m_prev, Wmh, Wmm, Whm, bm, out);
}

// round 7
// speedup vs baseline: 1.0183x; 1.0183x over previous
#include <cuda_runtime.h>

#define T_STEPS 256
#define BATCH   64
#define IN_DIM  512
#define HID     1024
#define MDIM    2048
#define NB      128
#define NT      512
#define SKU     48      // upd split-K count (Kc = 64)

// ---------------- static device scratch ----------------
__device__ float g_xh[(size_t)T_STEPS * BATCH * HID];   // x@Wxh + bh (64 MB)
__device__ float g_h[BATCH * HID];                      // h_t
__device__ float g_c[BATCH * HID];                      // running c = m @ Wmh.T
__device__ float g_dm[BATCH * MDIM];                    // delta m (active cols)
__device__ float g_cpart[32 * BATCH * HID];             // c-increment split-K partials
__device__ float g_upart[(size_t)SKU * BATCH * MDIM];   // upd split-K partials
__device__ unsigned g_cnt;
__device__ unsigned g_gen;
// dataflow counters (monotonic within a launch; reset at kernel start)
__device__ unsigned cnt_c[4];     // per 256-col h tile: phase-1 units done
__device__ unsigned cnt_h[4];     // per 256-col h tile: h units done (4/tile/step)
__device__ unsigned cnt_u[8];     // per 256-col out tile: phase-3 units done (48/tile/step when active)
__device__ unsigned cnt_out[8];   // per 256-col out tile: merge/copy units done (16/tile/step)

// ---------------- packed fp32x2 ----------------
__device__ __forceinline__ unsigned long long pack2(float a) {
    unsigned long long r;
    asm("mov.b64 %0, {%1, %1};" : "=l"(r) : "f"(a));
    return r;
}
__device__ __forceinline__ void ffma2(unsigned long long& c, unsigned long long a, unsigned long long b) {
    asm("fma.rn.f32x2 %0, %1, %2, %0;" : "+l"(c) : "l"(a), "l"(b));
}

// ---------------- dataflow sync primitives ----------------
__device__ __forceinline__ unsigned ldacq(const unsigned* p) {
    unsigned v;
    asm volatile("ld.acquire.gpu.global.u32 %0, [%1];" : "=r"(v) : "l"(p) : "memory");
    return v;
}
// block-wide: wait until *c >= tgt (thread 0 polls, then syncthreads)
__device__ __forceinline__ void waitge(const unsigned* c, unsigned tgt) {
    if (threadIdx.x == 0) {
        while (ldacq(c) < tgt) { }
    }
    __syncthreads();
}
// block-wide: release all prior writes, then bump counter
__device__ __forceinline__ void signal(unsigned* c) {
    __threadfence();
    __syncthreads();
    if (threadIdx.x == 0) atomicAdd(c, 1u);
}

// ---------------- startup grid barrier (all NB blocks co-resident) ----------
__device__ __forceinline__ void grid_barrier() {
    __threadfence();
    __syncthreads();
    if (threadIdx.x == 0) {
        volatile unsigned* vg = &g_gen;
        unsigned old = *vg;
        unsigned prev = atomicAdd(&g_cnt, 1u);
        if (prev == NB - 1) {
            atomicExch(&g_cnt, 0u);
            __threadfence();
            atomicAdd(&g_gen, 1u);
        } else {
            while (*vg == old) { __nanosleep(64); }
        }
    }
    __syncthreads();
}

// ---------------- 64x256 tile, 512 threads, 4x8 per thread ----------------
// As: [16][68] (As[k][row]); Bs: [16][260] (Bs[k][col])
__device__ __forceinline__ void tile_compute4(const float* As, const float* Bs,
                                              int ty, int tx, unsigned long long acc[4][4]) {
#pragma unroll
    for (int kk = 0; kk < 16; kk++) {
        float4 a0 = *(const float4*)(As + kk * 68 + ty * 4);
        const unsigned long long* bp = (const unsigned long long*)(Bs + kk * 260 + tx * 8);
        unsigned long long b0 = bp[0], b1 = bp[1], b2 = bp[2], b3 = bp[3];
        float a_s[4] = {a0.x, a0.y, a0.z, a0.w};
#pragma unroll
        for (int r = 0; r < 4; r++) {
            unsigned long long av = pack2(a_s[r]);
            ffma2(acc[r][0], av, b0);
            ffma2(acc[r][1], av, b1);
            ffma2(acc[r][2], av, b2);
            ffma2(acc[r][3], av, b3);
        }
    }
}

// ---------------- 64x256 tile, 256 threads, 8x8 per thread (prologue) -------
__device__ __forceinline__ void tile_compute8(const float* As, const float* Bs,
                                              int ty, int tx, unsigned long long acc[8][4]) {
#pragma unroll
    for (int kk = 0; kk < 16; kk++) {
        float4 a0 = *(const float4*)(As + kk * 68 + ty * 8);
        float4 a1 = *(const float4*)(As + kk * 68 + ty * 8 + 4);
        const unsigned long long* bp = (const unsigned long long*)(Bs + kk * 260 + tx * 8);
        unsigned long long b0 = bp[0], b1 = bp[1], b2 = bp[2], b3 = bp[3];
        float a_s[8] = {a0.x, a0.y, a0.z, a0.w, a1.x, a1.y, a1.z, a1.w};
#pragma unroll
        for (int r = 0; r < 8; r++) {
            unsigned long long av = pack2(a_s[r]);
            ffma2(acc[r][0], av, b0);
            ffma2(acc[r][1], av, b1);
            ffma2(acc[r][2], av, b2);
            ffma2(acc[r][3], av, b3);
        }
    }
}

// ---------------- prologue: g_xh = x @ Wxh + bh ----------------
__global__ __launch_bounds__(256) void xh_kernel(
    const float* __restrict__ X, const float* __restrict__ Wxh, const float* __restrict__ bh)
{
    __shared__ float As[16 * 68];
    __shared__ float Bs[16 * 260];
    const int tid = threadIdx.x;
    const int ty = tid >> 5, tx = tid & 31;
    const int colBase = blockIdx.x * 256;
    const int rowBase = blockIdx.y * 64;

    unsigned long long acc[8][4];
#pragma unroll
    for (int r = 0; r < 8; r++)
#pragma unroll
        for (int c = 0; c < 4; c++) acc[r][c] = 0ULL;

    for (int ch = 0; ch < 32; ch++) {
        int kb = ch << 4;
        {
            int row = tid >> 2, kl = (tid & 3) << 2;
            float4 v = *(const float4*)(X + (size_t)(rowBase + row) * IN_DIM + kb + kl);
            As[(kl + 0) * 68 + row] = v.x; As[(kl + 1) * 68 + row] = v.y;
            As[(kl + 2) * 68 + row] = v.z; As[(kl + 3) * 68 + row] = v.w;
        }
#pragma unroll
        for (int i = 0; i < 4; i++) {
            int g = tid + i * 256;
            int kl = g >> 6, col4 = (g & 63) << 2;
            float4 v = *(const float4*)(Wxh + (size_t)(kb + kl) * HID + colBase + col4);
            *(float4*)(Bs + kl * 260 + col4) = v;
        }
        __syncthreads();
        tile_compute8(As, Bs, ty, tx, acc);
        __syncthreads();
    }

#pragma unroll
    for (int r = 0; r < 8; r++) {
        int row = rowBase + ty * 8 + r;
        int jg = colBase + tx * 8;
#pragma unroll
        for (int c = 0; c < 4; c++) {
            float2 v = *(float2*)&acc[r][c];
            float2 bb = *(const float2*)(bh + jg + c * 2);
            v.x += bb.x; v.y += bb.y;
            *(float2*)(g_xh + (size_t)row * HID + jg + c * 2) = v;
        }
    }
}

// ---------------- persistent dataflow recurrence ----------------
__global__ __launch_bounds__(NT, 1) void rnn_persistent(
    const float* __restrict__ m_prev, const float* __restrict__ Wmh,
    const float* __restrict__ Wmm, const float* __restrict__ Whm,
    const float* __restrict__ bm, float* __restrict__ out)
{
    __shared__ float As[16 * 68];
    __shared__ float Bs[16 * 260];
    const int tid = threadIdx.x;
    const int ty = tid >> 5, tx = tid & 31;     // 4x8 thread tile
    const int bid = blockIdx.x;

    // reset dataflow counters (replay safety), then sync all blocks
    if (bid == 0 && tid == 0) {
#pragma unroll
        for (int i = 0; i < 4; i++) { cnt_c[i] = 0u; cnt_h[i] = 0u; }
#pragma unroll
        for (int i = 0; i < 8; i++) { cnt_u[i] = 0u; cnt_out[i] = 0u; }
    }
    grid_barrier();

    unsigned cum_c = 0;   // cumulative cnt_c target (same for all 4 tiles)

    for (int t = 0; t < T_STEPS; t++) {
        const float* mP = t ? (out + (size_t)(t - 1) * BATCH * MDIM) : m_prev;
        const int kcur = t ? min(__ffs(t), 8) : 8;
        const int kprev = (t <= 1) ? 8 : min(__ffs(t - 1), 8);
        const int nsplit = kprev * 4;                 // phase-1 splits (Kc=64)
        const float* dsrc = t ? g_dm : m_prev;
        cum_c += (unsigned)nsplit;

        // ========== stage 1: c-increment partials = dm @ Wmh.T ==========
        if (bid < nsplit * 4) {
            const int s = bid % nsplit;
            const int ct4 = bid / nsplit;
            const int colBase = ct4 * 256;
            const int kBase0 = s * 64;

            waitge(&cnt_h[ct4], 4u * (unsigned)t);          // WAR: h(t-1) consumed slab
            waitge(&cnt_out[s >> 2], 16u * (unsigned)t);    // RAW: dm tile ready

            unsigned long long acc[4][4];
#pragma unroll
            for (int r = 0; r < 4; r++)
#pragma unroll
                for (int c = 0; c < 4; c++) acc[r][c] = 0ULL;

#pragma unroll
            for (int ch = 0; ch < 4; ch++) {
                int kb = kBase0 + (ch << 4);
                if (tid < 256) {
                    int row = tid >> 2, kl = (tid & 3) << 2;
                    float4 v = __ldcg((const float4*)(dsrc + (size_t)row * MDIM + kb + kl));
                    As[(kl + 0) * 68 + row] = v.x; As[(kl + 1) * 68 + row] = v.y;
                    As[(kl + 2) * 68 + row] = v.z; As[(kl + 3) * 68 + row] = v.w;
                }
#pragma unroll
                for (int i = 0; i < 2; i++) {
                    int g = tid + i * 512;
                    int col = g >> 2, kl = (g & 3) << 2;
                    float4 v = *(const float4*)(Wmh + (size_t)(colBase + col) * MDIM + kb + kl);
                    Bs[(kl + 0) * 260 + col] = v.x; Bs[(kl + 1) * 260 + col] = v.y;
                    Bs[(kl + 2) * 260 + col] = v.z; Bs[(kl + 3) * 260 + col] = v.w;
                }
                __syncthreads();
                tile_compute4(As, Bs, ty, tx, acc);
                __syncthreads();
            }
#pragma unroll
            for (int r = 0; r < 4; r++) {
                int row = ty * 4 + r;
                size_t base = (size_t)s * (BATCH * HID) + (size_t)row * HID + colBase + tx * 8;
#pragma unroll
                for (int c = 0; c < 4; c++)
                    *(float2*)(g_cpart + base + c * 2) = *(float2*)&acc[r][c];
            }
            signal(&cnt_c[ct4]);
        }

        // ========== stage 2: h units (16 blocks; 64 cols x 64 rows each) ==========
        if (bid < 16) {
            const int ct4 = bid >> 2, part = bid & 3;
            waitge(&cnt_c[ct4], cum_c);

            const int row = tid >> 3;
            const int col = ct4 * 256 + part * 64 + (tid & 7) * 8;
            const size_t off = (size_t)row * HID + col;

            float4 s0 = make_float4(0.f, 0.f, 0.f, 0.f);
            float4 s1 = make_float4(0.f, 0.f, 0.f, 0.f);
            for (int p = 0; p < nsplit; p++) {
                const float* sl = g_cpart + (size_t)p * (BATCH * HID) + off;
                float4 a = __ldcg((const float4*)sl);
                float4 b = __ldcg((const float4*)(sl + 4));
                s0.x += a.x; s0.y += a.y; s0.z += a.z; s0.w += a.w;
                s1.x += b.x; s1.y += b.y; s1.z += b.z; s1.w += b.w;
            }
            float4 c0, c1;
            if (t) { c0 = *(const float4*)(g_c + off); c1 = *(const float4*)(g_c + off + 4); }
            else   { c0 = make_float4(0.f,0.f,0.f,0.f); c1 = make_float4(0.f,0.f,0.f,0.f); }
            c0.x += s0.x; c0.y += s0.y; c0.z += s0.z; c0.w += s0.w;
            c1.x += s1.x; c1.y += s1.y; c1.z += s1.z; c1.w += s1.w;
            *(float4*)(g_c + off) = c0;
            *(float4*)(g_c + off + 4) = c1;
            const float* xh = g_xh + (size_t)t * (BATCH * HID) + off;
            float4 x0 = *(const float4*)xh;
            float4 x1 = *(const float4*)(xh + 4);
            float4 h0 = make_float4(tanhf(x0.x + c0.x), tanhf(x0.y + c0.y),
                                    tanhf(x0.z + c0.z), tanhf(x0.w + c0.w));
            float4 h1 = make_float4(tanhf(x1.x + c1.x), tanhf(x1.y + c1.y),
                                    tanhf(x1.z + c1.z), tanhf(x1.w + c1.w));
            *(float4*)(g_h + off) = h0;
            *(float4*)(g_h + off + 4) = h1;
            signal(&cnt_h[ct4]);
        }

        // ========== stage 3: upd partials ([m|h] @ [Wmm|Whm].T), Kc=64 ==========
        for (int u = bid; u < SKU * kcur; u += NB) {
            const int ct = u / SKU, s = u - ct * SKU;
            const int colBase = ct * 256;
            const int kBase0 = s * 64;

            if (kBase0 >= MDIM) waitge(&cnt_h[(kBase0 - MDIM) >> 8], 4u * (unsigned)(t + 1));
            else                waitge(&cnt_out[kBase0 >> 8], 16u * (unsigned)t);
            waitge(&cnt_out[ct], 16u * (unsigned)t);     // WAR: merge(t-1) consumed slab

            unsigned long long acc[4][4];
#pragma unroll
            for (int r = 0; r < 4; r++)
#pragma unroll
                for (int c = 0; c < 4; c++) acc[r][c] = 0ULL;

#pragma unroll
            for (int ch = 0; ch < 4; ch++) {
                int kb = kBase0 + (ch << 4);
                if (tid < 256) {
                    int row = tid >> 2, kl = (tid & 3) << 2;
                    float4 v;
                    if (kb < MDIM) v = __ldcg((const float4*)(mP + (size_t)row * MDIM + kb + kl));
                    else           v = __ldcg((const float4*)(g_h + (size_t)row * HID + (kb - MDIM) + kl));
                    As[(kl + 0) * 68 + row] = v.x; As[(kl + 1) * 68 + row] = v.y;
                    As[(kl + 2) * 68 + row] = v.z; As[(kl + 3) * 68 + row] = v.w;
                }
#pragma unroll
                for (int i = 0; i < 2; i++) {
                    int g = tid + i * 512;
                    int col = g >> 2, kl = (g & 3) << 2;
                    int jg = colBase + col;
                    float4 v;
                    if (kb < MDIM) v = *(const float4*)(Wmm + (size_t)jg * MDIM + kb + kl);
                    else           v = *(const float4*)(Whm + (size_t)jg * HID + (kb - MDIM) + kl);
                    Bs[(kl + 0) * 260 + col] = v.x; Bs[(kl + 1) * 260 + col] = v.y;
                    Bs[(kl + 2) * 260 + col] = v.z; Bs[(kl + 3) * 260 + col] = v.w;
                }
                __syncthreads();
                tile_compute4(As, Bs, ty, tx, acc);
                __syncthreads();
            }
#pragma unroll
            for (int r = 0; r < 4; r++) {
                int row = ty * 4 + r;
                size_t base = (size_t)s * (BATCH * MDIM) + (size_t)row * MDIM + colBase + tx * 8;
#pragma unroll
                for (int c = 0; c < 4; c++)
                    *(float2*)(g_upart + base + c * 2) = *(float2*)&acc[r][c];
            }
            signal(&cnt_u[ct]);
        }

        // ========== stage 4: merge/copy (128 units; 16 cols x 64 rows each) ==========
        {
            const int ct8 = bid >> 4, part = bid & 15;
            const int row = tid >> 3;
            const int col = ct8 * 256 + part * 16 + (tid & 7) * 2;
            const size_t moff = (size_t)row * MDIM + col;
            float2 v;

            if (ct8 < kcur) {
                waitge(&cnt_u[ct8], 48u * (unsigned)(t / (1 << ct8) + 1));
                waitge(&cnt_out[ct8], 16u * (unsigned)t);      // mP tile for dm
                v = *(const float2*)(bm + col);
#pragma unroll 8
                for (int p = 0; p < SKU; p++) {
                    float2 w = __ldcg((const float2*)(g_upart + (size_t)p * (BATCH * MDIM) + moff));
                    v.x += w.x; v.y += w.y;
                }
                float2 mo = __ldcg((const float2*)(mP + moff));
                *(float2*)(g_dm + moff) = make_float2(v.x - mo.x, v.y - mo.y);
            } else {
                waitge(&cnt_out[ct8], 16u * (unsigned)t);
                v = __ldcg((const float2*)(mP + moff));
            }
            *(float2*)(out + (size_t)t * (BATCH * MDIM) + moff) = v;
            if (t == T_STEPS - 1)
                *(float2*)(out + (size_t)T_STEPS * (BATCH * MDIM) + moff) = v;
            signal(&cnt_out[ct8]);
        }
    }
}

// ---------------- host ----------------
extern "C" void kernel_launch(void* const* d_in, const int* in_sizes, int n_in,
                              void* d_out, int out_size)
{
    const float* x      = (const float*)d_in[0];
    const float* m_prev = (const float*)d_in[1];
    const float* Wxh    = (const float*)d_in[2];
    const float* Whm    = (const float*)d_in[3];
    const float* Wmm    = (const float*)d_in[4];
    const float* Wmh    = (const float*)d_in[5];
    const float* bm     = (const float*)d_in[6];
    const float* bh     = (const float*)d_in[7];
    float* out = (float*)d_out;
    (void)in_sizes; (void)n_in; (void)out_size;

    xh_kernel<<<dim3(4, 256), 256>>>(x, Wxh, bh);
    rnn_persistent<<<NB, NT>>>(m_prev, Wmh, Wmm, Whm, bm, out);
}

// round 8
// speedup vs baseline: 2.1571x; 2.1182x over previous
#include <cuda_runtime.h>

#define T_STEPS 256
#define BATCH   64
#define IN_DIM  512
#define HID     1024
#define MDIM    2048
#define NB      128
#define NT      512
#define BM      (BATCH*MDIM)   // 131072
#define BH      (BATCH*HID)    // 65536

// ---------------- static device scratch ----------------
__device__ float g_xh[(size_t)T_STEPS * BH];  // x@Wxh + bh (64 MB)
__device__ float g_h[BH];                     // h_t
__device__ float g_c[BH];                     // running c = m @ Wmh.T (red-accumulated)
__device__ unsigned g_cnt, g_gen;
__device__ unsigned cnt_c[8];     // per 128-col h tile: phase1 units done (16/step)
__device__ unsigned cnt_h[4];     // per 256-col h tile: h units done (4/step)
__device__ unsigned cnt_out[8];   // per 256-col out tile completion
__device__ unsigned cnt_init[8];  // per 256-col out tile bm-init events

// ---------------- packed fp32x2 ----------------
__device__ __forceinline__ unsigned long long pack2(float a) {
    unsigned long long r;
    asm("mov.b64 %0, {%1, %1};" : "=l"(r) : "f"(a));
    return r;
}
__device__ __forceinline__ void ffma2(unsigned long long& c, unsigned long long a, unsigned long long b) {
    asm("fma.rn.f32x2 %0, %1, %2, %0;" : "+l"(c) : "l"(a), "l"(b));
}

// ---------------- L2-side vector reduction ----------------
__device__ __forceinline__ void red_add_v4(float* p, float4 v) {
    asm volatile("red.global.add.v4.f32 [%0], {%1,%2,%3,%4};"
                 :: "l"(p), "f"(v.x), "f"(v.y), "f"(v.z), "f"(v.w) : "memory");
}

// ---------------- sync primitives (proven pattern from R6/R7) ----------------
__device__ __forceinline__ unsigned ldacq(const unsigned* p) {
    unsigned v;
    asm volatile("ld.acquire.gpu.global.u32 %0, [%1];" : "=r"(v) : "l"(p) : "memory");
    return v;
}
__device__ __forceinline__ void waitge(const unsigned* c, unsigned tgt) {
    if (threadIdx.x == 0) { while (ldacq(c) < tgt) { } }
    __syncthreads();
}
__device__ __forceinline__ void sigrel(unsigned* c) {
    __threadfence();
    __syncthreads();
    if (threadIdx.x == 0) atomicAdd(c, 1u);
}
__device__ __forceinline__ void grid_barrier() {
    __threadfence();
    __syncthreads();
    if (threadIdx.x == 0) {
        volatile unsigned* vg = &g_gen;
        unsigned old = *vg;
        unsigned prev = atomicAdd(&g_cnt, 1u);
        if (prev == NB - 1) {
            atomicExch(&g_cnt, 0u);
            __threadfence();
            atomicAdd(&g_gen, 1u);
        } else {
            while (*vg == old) { __nanosleep(64); }
        }
    }
    __syncthreads();
}

__device__ __forceinline__ int kval_d(int t) { return t ? min(__ffs(t), 8) : 8; }

// ---------------- tile compute: 64 rows x 128 cols, 512 thr, 4x4 ----------
// As[16][68] (As[k][row]); Bs[16][132] (Bs[k][col]); ty=tid>>5 (row grp), tx=tid&31
__device__ __forceinline__ void tile_compute44(const float* As, const float* Bs,
                                               int ty, int tx, unsigned long long acc[4][2]) {
#pragma unroll
    for (int kk = 0; kk < 16; kk++) {
        float4 a = *(const float4*)(As + kk * 68 + ty * 4);
        const unsigned long long* bp = (const unsigned long long*)(Bs + kk * 132 + tx * 4);
        unsigned long long b0 = bp[0], b1 = bp[1];
        float as[4] = {a.x, a.y, a.z, a.w};
#pragma unroll
        for (int r = 0; r < 4; r++) {
            unsigned long long av = pack2(as[r]);
            ffma2(acc[r][0], av, b0);
            ffma2(acc[r][1], av, b1);
        }
    }
}
// ---------------- tile compute: 64 rows x 256 cols, 512 thr, 4x8 ----------
__device__ __forceinline__ void tile_compute48(const float* As, const float* Bs,
                                               int ty, int tx, unsigned long long acc[4][4]) {
#pragma unroll
    for (int kk = 0; kk < 16; kk++) {
        float4 a = *(const float4*)(As + kk * 68 + ty * 4);
        const unsigned long long* bp = (const unsigned long long*)(Bs + kk * 260 + tx * 8);
        unsigned long long b0 = bp[0], b1 = bp[1], b2 = bp[2], b3 = bp[3];
        float as[4] = {a.x, a.y, a.z, a.w};
#pragma unroll
        for (int r = 0; r < 4; r++) {
            unsigned long long av = pack2(as[r]);
            ffma2(acc[r][0], av, b0);
            ffma2(acc[r][1], av, b1);
            ffma2(acc[r][2], av, b2);
            ffma2(acc[r][3], av, b3);
        }
    }
}
// ---------------- 64x256, 256 thr, 8x8 (prologue only) ----------
__device__ __forceinline__ void tile_compute8(const float* As, const float* Bs,
                                              int ty, int tx, unsigned long long acc[8][4]) {
#pragma unroll
    for (int kk = 0; kk < 16; kk++) {
        float4 a0 = *(const float4*)(As + kk * 68 + ty * 8);
        float4 a1 = *(const float4*)(As + kk * 68 + ty * 8 + 4);
        const unsigned long long* bp = (const unsigned long long*)(Bs + kk * 260 + tx * 8);
        unsigned long long b0 = bp[0], b1 = bp[1], b2 = bp[2], b3 = bp[3];
        float as[8] = {a0.x, a0.y, a0.z, a0.w, a1.x, a1.y, a1.z, a1.w};
#pragma unroll
        for (int r = 0; r < 8; r++) {
            unsigned long long av = pack2(as[r]);
            ffma2(acc[r][0], av, b0);
            ffma2(acc[r][1], av, b1);
            ffma2(acc[r][2], av, b2);
            ffma2(acc[r][3], av, b3);
        }
    }
}

// ---------------- prologue: g_xh = x @ Wxh + bh ----------------
__global__ __launch_bounds__(256) void xh_kernel(
    const float* __restrict__ X, const float* __restrict__ Wxh, const float* __restrict__ bh)
{
    __shared__ float As[16 * 68];
    __shared__ float Bs[16 * 260];
    const int tid = threadIdx.x;
    const int ty = tid >> 5, tx = tid & 31;
    const int colBase = blockIdx.x * 256;
    const int rowBase = blockIdx.y * 64;

    unsigned long long acc[8][4];
#pragma unroll
    for (int r = 0; r < 8; r++)
#pragma unroll
        for (int c = 0; c < 4; c++) acc[r][c] = 0ULL;

    for (int ch = 0; ch < 32; ch++) {
        int kb = ch << 4;
        {
            int row = tid >> 2, kl = (tid & 3) << 2;
            float4 v = *(const float4*)(X + (size_t)(rowBase + row) * IN_DIM + kb + kl);
            As[(kl + 0) * 68 + row] = v.x; As[(kl + 1) * 68 + row] = v.y;
            As[(kl + 2) * 68 + row] = v.z; As[(kl + 3) * 68 + row] = v.w;
        }
#pragma unroll
        for (int i = 0; i < 4; i++) {
            int g = tid + i * 256;
            int kl = g >> 6, col4 = (g & 63) << 2;
            float4 v = *(const float4*)(Wxh + (size_t)(kb + kl) * HID + colBase + col4);
            *(float4*)(Bs + kl * 260 + col4) = v;
        }
        __syncthreads();
        tile_compute8(As, Bs, ty, tx, acc);
        __syncthreads();
    }
#pragma unroll
    for (int r = 0; r < 8; r++) {
        int row = rowBase + ty * 8 + r;
        int jg = colBase + tx * 8;
#pragma unroll
        for (int c = 0; c < 4; c++) {
            float2 v = *(float2*)&acc[r][c];
            float2 bb = *(const float2*)(bh + jg + c * 2);
            v.x += bb.x; v.y += bb.y;
            *(float2*)(g_xh + (size_t)row * HID + jg + c * 2) = v;
        }
    }
}

// ---------------- persistent dataflow recurrence ----------------
__global__ __launch_bounds__(NT, 1) void rnn_persistent(
    const float* __restrict__ m_prev, const float* __restrict__ Wmh,
    const float* __restrict__ Wmm, const float* __restrict__ Whm,
    const float* __restrict__ bm, float* __restrict__ out)
{
    __shared__ float As[16 * 68];
    __shared__ float Bs[16 * 260];
    const int tid = threadIdx.x;
    const int ty = tid >> 5, tx = tid & 31;
    const int bid = blockIdx.x;
    const int ft = bid * NT + tid;    // [0, 65536)

    // ---- startup: reset counters, zero g_c, bm-init out[0] ----
    if (bid == 0 && tid == 0) {
#pragma unroll
        for (int i = 0; i < 8; i++) { cnt_c[i] = 0; cnt_out[i] = 0; cnt_init[i] = 0; }
#pragma unroll
        for (int i = 0; i < 4; i++) cnt_h[i] = 0;
    }
    g_c[ft] = 0.0f;
    {   // out[0] = bm (all 8 tiles active at t=0)
        int col = (ft * 2) & (MDIM - 1);
        *(float2*)(out + (size_t)ft * 2) = *(const float2*)(bm + col);
    }
    grid_barrier();

    int eo[8];   // cnt_out totals through step t-1
    int eI[8];   // cnt_init totals scheduled through step t-1
#pragma unroll
    for (int j = 0; j < 8; j++) { eo[j] = 0; eI[j] = 0; }

    for (int t = 0; t < T_STEPS; t++) {
        const float* mP  = t ? (out + (size_t)(t - 1) * BM) : m_prev;
        const float* mPP = (t >= 2) ? (out + (size_t)(t - 2) * BM) : m_prev;
        const int kcur  = kval_d(t);
        const int kprev = (t <= 1) ? 8 : kval_d(t - 1);

        // ====== stage 1: phase1 — red(dm @ Wmh.T) into g_c (128 units) ======
        {
            const int ct4 = bid >> 4;          // 0..7 (128-col tile of HID)
            const int s   = bid & 15;          // split
            const int Kc  = kprev << 4;
            const int kb0 = s * Kc;
            waitge(&cnt_h[ct4 >> 1], 4u * (unsigned)t);   // WAR: h(t-1) read g_c
            if (t) {
                const int jlo = kb0 >> 8, jhi = (kb0 + Kc - 1) >> 8;
#pragma unroll
                for (int j = 0; j < 8; j++)
                    if (j >= jlo && j <= jhi) waitge(&cnt_out[j], (unsigned)eo[j]);
            }
            unsigned long long acc[4][2];
#pragma unroll
            for (int r = 0; r < 4; r++) { acc[r][0] = 0ULL; acc[r][1] = 0ULL; }
            const int colBase = ct4 * 128;
            for (int ch = 0; ch < kprev; ch++) {
                int kb = kb0 + (ch << 4);
                if (tid < 256) {
                    int row = tid >> 2, kl = (tid & 3) << 2;
                    float4 a;
                    if (t) {
                        float4 p = __ldcg((const float4*)(mP  + (size_t)row * MDIM + kb + kl));
                        float4 q = __ldcg((const float4*)(mPP + (size_t)row * MDIM + kb + kl));
                        a = make_float4(p.x - q.x, p.y - q.y, p.z - q.z, p.w - q.w);
                    } else {
                        a = *(const float4*)(m_prev + (size_t)row * MDIM + kb + kl);
                    }
                    As[(kl + 0) * 68 + row] = a.x; As[(kl + 1) * 68 + row] = a.y;
                    As[(kl + 2) * 68 + row] = a.z; As[(kl + 3) * 68 + row] = a.w;
                }
                {
                    int col = tid >> 2, kl = (tid & 3) << 2;
                    float4 v = *(const float4*)(Wmh + (size_t)(colBase + col) * MDIM + kb + kl);
                    Bs[(kl + 0) * 132 + col] = v.x; Bs[(kl + 1) * 132 + col] = v.y;
                    Bs[(kl + 2) * 132 + col] = v.z; Bs[(kl + 3) * 132 + col] = v.w;
                }
                __syncthreads();
                tile_compute44(As, Bs, ty, tx, acc);
                __syncthreads();
            }
#pragma unroll
            for (int r = 0; r < 4; r++) {
                float4 v = make_float4(((float2*)&acc[r][0])->x, ((float2*)&acc[r][0])->y,
                                       ((float2*)&acc[r][1])->x, ((float2*)&acc[r][1])->y);
                red_add_v4(g_c + (size_t)(ty * 4 + r) * HID + colBase + tx * 4, v);
            }
            sigrel(&cnt_c[ct4]);
        }

        // ====== stage 1b: bm-init out[t+1] active tiles (no deps) ======
        if (t + 1 < T_STEPS) {
            int kn = kval_d(t + 1);
            int j = bid - 120;
            if (j >= 0 && j < kn) {
                float* dst = out + (size_t)(t + 1) * BM;
                for (int idx = tid; idx < 4096; idx += NT) {
                    int row = idx >> 6, c4 = (idx & 63) << 2;
                    *(float4*)(dst + (size_t)row * MDIM + j * 256 + c4) =
                        *(const float4*)(bm + j * 256 + c4);
                }
                sigrel(&cnt_init[j]);
            }
        }

        // ====== stage 2: h = tanh(xh_t + c) (16 units) ======
        if (bid < 16) {
            const int j = bid >> 2, q = bid & 3;
            waitge(&cnt_c[2 * j],     16u * (unsigned)(t + 1));
            waitge(&cnt_c[2 * j + 1], 16u * (unsigned)(t + 1));
            const int row = tid >> 3;
            const int col = j * 256 + q * 64 + (tid & 7) * 8;
            const size_t off = (size_t)row * HID + col;
            float4 c0 = __ldcg((const float4*)(g_c + off));
            float4 c1 = __ldcg((const float4*)(g_c + off + 4));
            const float* xh = g_xh + (size_t)t * BH + off;
            float4 x0 = *(const float4*)xh;
            float4 x1 = *(const float4*)(xh + 4);
            float4 h0 = make_float4(tanhf(x0.x + c0.x), tanhf(x0.y + c0.y),
                                    tanhf(x0.z + c0.z), tanhf(x0.w + c0.w));
            float4 h1 = make_float4(tanhf(x1.x + c1.x), tanhf(x1.y + c1.y),
                                    tanhf(x1.z + c1.z), tanhf(x1.w + c1.w));
            *(float4*)(g_h + off) = h0;
            *(float4*)(g_h + off + 4) = h1;
            sigrel(&cnt_h[j]);
        }

        // ====== stage 3: phase3 — red([m|h] @ [Wmm|Whm].T) into out[t] ======
        {
            const int sp    = (kcur <= 2) ? 64 : (kcur <= 4 ? 32 : 16);  // mode-B splits
            const int units = (kcur == 1) ? 128 : kcur * sp;
            if (bid < units) {
                int ct256, colBase, s, Kc3;
                bool wide;
                if (kcur == 1) { wide = false; ct256 = 0; colBase = (bid >> 6) * 128; s = bid & 63; Kc3 = 48; }
                else           { wide = true;  ct256 = bid / sp; colBase = ct256 * 256; s = bid % sp; Kc3 = 3072 / sp; }
                const int kb0 = s * Kc3;
                // waits
#pragma unroll
                for (int j = 0; j < 8; j++)
                    if (j == ct256) waitge(&cnt_init[j], (unsigned)eI[j]);
                {
                    const int mk1 = min(kb0 + Kc3, MDIM);
                    if (t && mk1 > kb0) {
                        const int jlo = kb0 >> 8, jhi = (mk1 - 1) >> 8;
#pragma unroll
                        for (int j = 0; j < 8; j++)
                            if (j >= jlo && j <= jhi) waitge(&cnt_out[j], (unsigned)eo[j]);
                    }
                    const int hk0 = max(kb0, MDIM), hk1 = min(kb0 + Kc3, 3072);
                    if (hk1 > hk0) {
                        const int jlo = (hk0 - MDIM) >> 8, jhi = (hk1 - 1 - MDIM) >> 8;
#pragma unroll
                        for (int j = 0; j < 4; j++)
                            if (j >= jlo && j <= jhi) waitge(&cnt_h[j], 4u * (unsigned)(t + 1));
                    }
                }
                unsigned long long acc[4][4];
#pragma unroll
                for (int r = 0; r < 4; r++)
#pragma unroll
                    for (int c = 0; c < 4; c++) acc[r][c] = 0ULL;

                const int chunks = Kc3 >> 4;
                for (int ch = 0; ch < chunks; ch++) {
                    int kb = kb0 + (ch << 4);
                    if (tid < 256) {
                        int row = tid >> 2, kl = (tid & 3) << 2;
                        float4 v;
                        if (kb < MDIM) v = __ldcg((const float4*)(mP + (size_t)row * MDIM + kb + kl));
                        else           v = __ldcg((const float4*)(g_h + (size_t)row * HID + (kb - MDIM) + kl));
                        As[(kl + 0) * 68 + row] = v.x; As[(kl + 1) * 68 + row] = v.y;
                        As[(kl + 2) * 68 + row] = v.z; As[(kl + 3) * 68 + row] = v.w;
                    }
                    if (wide) {
#pragma unroll
                        for (int i = 0; i < 2; i++) {
                            int g = tid + i * NT;
                            int col = g >> 2, kl = (g & 3) << 2;
                            int jg = colBase + col;
                            float4 v;
                            if (kb < MDIM) v = *(const float4*)(Wmm + (size_t)jg * MDIM + kb + kl);
                            else           v = *(const float4*)(Whm + (size_t)jg * HID + (kb - MDIM) + kl);
                            Bs[(kl + 0) * 260 + col] = v.x; Bs[(kl + 1) * 260 + col] = v.y;
                            Bs[(kl + 2) * 260 + col] = v.z; Bs[(kl + 3) * 260 + col] = v.w;
                        }
                    } else {
                        int col = tid >> 2, kl = (tid & 3) << 2;
                        int jg = colBase + col;
                        float4 v;
                        if (kb < MDIM) v = *(const float4*)(Wmm + (size_t)jg * MDIM + kb + kl);
                        else           v = *(const float4*)(Whm + (size_t)jg * HID + (kb - MDIM) + kl);
                        Bs[(kl + 0) * 132 + col] = v.x; Bs[(kl + 1) * 132 + col] = v.y;
                        Bs[(kl + 2) * 132 + col] = v.z; Bs[(kl + 3) * 132 + col] = v.w;
                    }
                    __syncthreads();
                    if (wide) tile_compute48(As, Bs, ty, tx, acc);
                    else      tile_compute44(As, Bs, ty, tx, (unsigned long long(*)[2])acc);
                    __syncthreads();
                }
                float* obase = out + (size_t)t * BM;
                if (wide) {
#pragma unroll
                    for (int r = 0; r < 4; r++) {
                        float2 a0 = *(float2*)&acc[r][0], a1 = *(float2*)&acc[r][1];
                        float2 a2 = *(float2*)&acc[r][2], a3 = *(float2*)&acc[r][3];
                        float* p = obase + (size_t)(ty * 4 + r) * MDIM + colBase + tx * 8;
                        red_add_v4(p,     make_float4(a0.x, a0.y, a1.x, a1.y));
                        red_add_v4(p + 4, make_float4(a2.x, a2.y, a3.x, a3.y));
                    }
                } else {
                    unsigned long long (*a2)[2] = (unsigned long long(*)[2])acc;
#pragma unroll
                    for (int r = 0; r < 4; r++) {
                        float2 a0 = *(float2*)&a2[r][0], a1 = *(float2*)&a2[r][1];
                        red_add_v4(obase + (size_t)(ty * 4 + r) * MDIM + colBase + tx * 4,
                                   make_float4(a0.x, a0.y, a1.x, a1.y));
                    }
                }
                sigrel(&cnt_out[ct256]);
            }
        }

        // ====== stage 4: copy inactive tiles (tiles >= kcur) ======
        {
            const int ct8 = bid >> 4, part = bid & 15;
            if (ct8 >= kcur) {
#pragma unroll
                for (int j = 0; j < 8; j++)
                    if (j == ct8) waitge(&cnt_out[j], (unsigned)eo[j]);
                const int row = tid >> 3;
                const int col = ct8 * 256 + part * 16 + (tid & 7) * 2;
                const size_t moff = (size_t)row * MDIM + col;
                float2 v = __ldcg((const float2*)(mP + moff));
                *(float2*)(out + (size_t)t * BM + moff) = v;
                sigrel(&cnt_out[ct8]);
            }
        }

        // ====== end-of-step bookkeeping ======
        {
            const int sp = (kcur <= 2) ? 64 : (kcur <= 4 ? 32 : 16);
            const int actsig = (kcur == 1) ? 128 : sp;
#pragma unroll
            for (int j = 0; j < 8; j++) eo[j] += (j < kcur) ? actsig : 16;
            if (t + 1 < T_STEPS) {
                int kn = kval_d(t + 1);
#pragma unroll
                for (int j = 0; j < 8; j++) if (j < kn) eI[j]++;
            }
        }
    }

    // ---- final: m_T = out[255] ----
#pragma unroll
    for (int j = 0; j < 8; j++) waitge(&cnt_out[j], (unsigned)eo[j]);
    {
        size_t o = (size_t)ft * 2;
        float2 v = __ldcg((const float2*)(out + (size_t)(T_STEPS - 1) * BM + o));
        *(float2*)(out + (size_t)T_STEPS * BM + o) = v;
    }
}

// ---------------- host ----------------
extern "C" void kernel_launch(void* const* d_in, const int* in_sizes, int n_in,
                              void* d_out, int out_size)
{
    const float* x      = (const float*)d_in[0];
    const float* m_prev = (const float*)d_in[1];
    const float* Wxh    = (const float*)d_in[2];
    const float* Whm    = (const float*)d_in[3];
    const float* Wmm    = (const float*)d_in[4];
    const float* Wmh    = (const float*)d_in[5];
    const float* bm     = (const float*)d_in[6];
    const float* bh     = (const float*)d_in[7];
    float* out = (float*)d_out;
    (void)in_sizes; (void)n_in; (void)out_size;

    xh_kernel<<<dim3(4, 256), 256>>>(x, Wxh, bh);
    rnn_persistent<<<NB, NT>>>(m_prev, Wmh, Wmm, Whm, bm, out);
}

// round 9
// speedup vs baseline: 2.2538x; 1.0448x over previous
#include <cuda_runtime.h>

#define T_STEPS 256
#define BATCH   64
#define IN_DIM  512
#define HID     1024
#define MDIM    2048
#define NB      128
#define NT      512
#define BM      (BATCH*MDIM)   // 131072
#define BH      (BATCH*HID)    // 65536

// ---------------- static device scratch ----------------
__device__ float g_xh[(size_t)T_STEPS * BH];  // x@Wxh + bh (64 MB)
__device__ float g_c[BH];                     // running c = m @ Wmh.T (red-accumulated)
__device__ unsigned g_cnt, g_gen;
__device__ unsigned cnt_c[8];     // per 128-col c tile: phase1 units done (16/step)
__device__ unsigned cnt_out[8];   // per 256-col out tile completion
__device__ unsigned cnt_init[8];  // per 256-col out tile bm-init events

// ---------------- packed fp32x2 ----------------
__device__ __forceinline__ unsigned long long pack2(float a) {
    unsigned long long r;
    asm("mov.b64 %0, {%1, %1};" : "=l"(r) : "f"(a));
    return r;
}
__device__ __forceinline__ void ffma2(unsigned long long& c, unsigned long long a, unsigned long long b) {
    asm("fma.rn.f32x2 %0, %1, %2, %0;" : "+l"(c) : "l"(a), "l"(b));
}

// ---------------- L2-side vector reduction ----------------
__device__ __forceinline__ void red_add_v4(float* p, float4 v) {
    asm volatile("red.global.add.v4.f32 [%0], {%1,%2,%3,%4};"
                 :: "l"(p), "f"(v.x), "f"(v.y), "f"(v.z), "f"(v.w) : "memory");
}

// ---------------- sync primitives ----------------
__device__ __forceinline__ unsigned ldacq(const unsigned* p) {
    unsigned v;
    asm volatile("ld.acquire.gpu.global.u32 %0, [%1];" : "=r"(v) : "l"(p) : "memory");
    return v;
}
__device__ __forceinline__ void waitge(const unsigned* c, unsigned tgt) {
    if (threadIdx.x == 0) { while (ldacq(c) < tgt) { } }
    __syncthreads();
}
__device__ __forceinline__ void sigrel(unsigned* c) {
    __threadfence();
    __syncthreads();
    if (threadIdx.x == 0) atomicAdd(c, 1u);
}
__device__ __forceinline__ void grid_barrier() {
    __threadfence();
    __syncthreads();
    if (threadIdx.x == 0) {
        volatile unsigned* vg = &g_gen;
        unsigned old = *vg;
        unsigned prev = atomicAdd(&g_cnt, 1u);
        if (prev == NB - 1) {
            atomicExch(&g_cnt, 0u);
            __threadfence();
            atomicAdd(&g_gen, 1u);
        } else {
            while (*vg == old) { __nanosleep(64); }
        }
    }
    __syncthreads();
}

__device__ __forceinline__ int kval_d(int t) { return t ? min(__ffs(t), 8) : 8; }

// ---------------- tile compute: 64 rows x 128 cols, 512 thr, 4x4 ----------
__device__ __forceinline__ void tile_compute44(const float* As, const float* Bs,
                                               int ty, int tx, unsigned long long acc[4][2]) {
#pragma unroll
    for (int kk = 0; kk < 16; kk++) {
        float4 a = *(const float4*)(As + kk * 68 + ty * 4);
        const unsigned long long* bp = (const unsigned long long*)(Bs + kk * 132 + tx * 4);
        unsigned long long b0 = bp[0], b1 = bp[1];
        float as[4] = {a.x, a.y, a.z, a.w};
#pragma unroll
        for (int r = 0; r < 4; r++) {
            unsigned long long av = pack2(as[r]);
            ffma2(acc[r][0], av, b0);
            ffma2(acc[r][1], av, b1);
        }
    }
}
// ---------------- tile compute: 64 rows x 256 cols, 512 thr, 4x8 ----------
__device__ __forceinline__ void tile_compute48(const float* As, const float* Bs,
                                               int ty, int tx, unsigned long long acc[4][4]) {
#pragma unroll
    for (int kk = 0; kk < 16; kk++) {
        float4 a = *(const float4*)(As + kk * 68 + ty * 4);
        const unsigned long long* bp = (const unsigned long long*)(Bs + kk * 260 + tx * 8);
        unsigned long long b0 = bp[0], b1 = bp[1], b2 = bp[2], b3 = bp[3];
        float as[4] = {a.x, a.y, a.z, a.w};
#pragma unroll
        for (int r = 0; r < 4; r++) {
            unsigned long long av = pack2(as[r]);
            ffma2(acc[r][0], av, b0);
            ffma2(acc[r][1], av, b1);
            ffma2(acc[r][2], av, b2);
            ffma2(acc[r][3], av, b3);
        }
    }
}
// ---------------- 64x256, 256 thr, 8x8 (prologue only) ----------
__device__ __forceinline__ void tile_compute8(const float* As, const float* Bs,
                                              int ty, int tx, unsigned long long acc[8][4]) {
#pragma unroll
    for (int kk = 0; kk < 16; kk++) {
        float4 a0 = *(const float4*)(As + kk * 68 + ty * 8);
        float4 a1 = *(const float4*)(As + kk * 68 + ty * 8 + 4);
        const unsigned long long* bp = (const unsigned long long*)(Bs + kk * 260 + tx * 8);
        unsigned long long b0 = bp[0], b1 = bp[1], b2 = bp[2], b3 = bp[3];
        float as[8] = {a0.x, a0.y, a0.z, a0.w, a1.x, a1.y, a1.z, a1.w};
#pragma unroll
        for (int r = 0; r < 8; r++) {
            unsigned long long av = pack2(as[r]);
            ffma2(acc[r][0], av, b0);
            ffma2(acc[r][1], av, b1);
            ffma2(acc[r][2], av, b2);
            ffma2(acc[r][3], av, b3);
        }
    }
}

// ---------------- prologue: g_xh = x @ Wxh + bh ----------------
__global__ __launch_bounds__(256) void xh_kernel(
    const float* __restrict__ X, const float* __restrict__ Wxh, const float* __restrict__ bh)
{
    __shared__ float As[16 * 68];
    __shared__ float Bs[16 * 260];
    const int tid = threadIdx.x;
    const int ty = tid >> 5, tx = tid & 31;
    const int colBase = blockIdx.x * 256;
    const int rowBase = blockIdx.y * 64;

    unsigned long long acc[8][4];
#pragma unroll
    for (int r = 0; r < 8; r++)
#pragma unroll
        for (int c = 0; c < 4; c++) acc[r][c] = 0ULL;

    for (int ch = 0; ch < 32; ch++) {
        int kb = ch << 4;
        {
            int row = tid >> 2, kl = (tid & 3) << 2;
            float4 v = *(const float4*)(X + (size_t)(rowBase + row) * IN_DIM + kb + kl);
            As[(kl + 0) * 68 + row] = v.x; As[(kl + 1) * 68 + row] = v.y;
            As[(kl + 2) * 68 + row] = v.z; As[(kl + 3) * 68 + row] = v.w;
        }
#pragma unroll
        for (int i = 0; i < 4; i++) {
            int g = tid + i * 256;
            int kl = g >> 6, col4 = (g & 63) << 2;
            float4 v = *(const float4*)(Wxh + (size_t)(kb + kl) * HID + colBase + col4);
            *(float4*)(Bs + kl * 260 + col4) = v;
        }
        __syncthreads();
        tile_compute8(As, Bs, ty, tx, acc);
        __syncthreads();
    }
#pragma unroll
    for (int r = 0; r < 8; r++) {
        int row = rowBase + ty * 8 + r;
        int jg = colBase + tx * 8;
#pragma unroll
        for (int c = 0; c < 4; c++) {
            float2 v = *(float2*)&acc[r][c];
            float2 bb = *(const float2*)(bh + jg + c * 2);
            v.x += bb.x; v.y += bb.y;
            *(float2*)(g_xh + (size_t)row * HID + jg + c * 2) = v;
        }
    }
}

// ---------------- persistent dataflow recurrence ----------------
__global__ __launch_bounds__(NT, 1) void rnn_persistent(
    const float* __restrict__ m_prev, const float* __restrict__ Wmh,
    const float* __restrict__ Wmm, const float* __restrict__ Whm,
    const float* __restrict__ bm, float* __restrict__ out)
{
    __shared__ float As[16 * 68];
    __shared__ float Bs[16 * 260];
    const int tid = threadIdx.x;
    const int ty = tid >> 5, tx = tid & 31;
    const int bid = blockIdx.x;
    const int ft = bid * NT + tid;    // [0, 65536)

    // ---- startup: reset counters, zero g_c, bm-init out[0] ----
    if (bid == 0 && tid == 0) {
#pragma unroll
        for (int i = 0; i < 8; i++) { cnt_c[i] = 0; cnt_out[i] = 0; cnt_init[i] = 0; }
    }
    g_c[ft] = 0.0f;
    {   // out[0] = bm (all 8 tiles active at t=0)
        int col = (ft * 2) & (MDIM - 1);
        *(float2*)(out + (size_t)ft * 2) = *(const float2*)(bm + col);
    }
    grid_barrier();

    int eo[8];   // cnt_out totals through step t-1
    int eI[8];   // cnt_init totals scheduled through step t-1
#pragma unroll
    for (int j = 0; j < 8; j++) { eo[j] = 0; eI[j] = 0; }

    for (int t = 0; t < T_STEPS; t++) {
        const float* mP  = t ? (out + (size_t)(t - 1) * BM) : m_prev;
        const float* mPP = (t >= 2) ? (out + (size_t)(t - 2) * BM) : m_prev;
        const int kcur  = kval_d(t);
        const int kprev = (t <= 1) ? 8 : kval_d(t - 1);

        // ====== stage 1: phase1 — red(dm @ Wmh.T) into g_c (128 units) ======
        {
            const int ct4 = bid >> 4;          // 0..7 (128-col tile of HID)
            const int s   = bid & 15;          // split
            const int Kc  = kprev << 4;
            const int kb0 = s * Kc;
            // RAW (dm tiles of step t-1) + WAR (all g_c readers of step t-1
            // signalled cnt_out on active tiles j < kprev)
            if (t) {
#pragma unroll
                for (int j = 0; j < 8; j++)
                    if (j < kprev) waitge(&cnt_out[j], (unsigned)eo[j]);
            }
            unsigned long long acc[4][2];
#pragma unroll
            for (int r = 0; r < 4; r++) { acc[r][0] = 0ULL; acc[r][1] = 0ULL; }
            const int colBase = ct4 * 128;
            for (int ch = 0; ch < kprev; ch++) {
                int kb = kb0 + (ch << 4);
                if (tid < 256) {
                    int row = tid >> 2, kl = (tid & 3) << 2;
                    float4 a;
                    if (t) {
                        float4 p = __ldcg((const float4*)(mP  + (size_t)row * MDIM + kb + kl));
                        float4 q = __ldcg((const float4*)(mPP + (size_t)row * MDIM + kb + kl));
                        a = make_float4(p.x - q.x, p.y - q.y, p.z - q.z, p.w - q.w);
                    } else {
                        a = *(const float4*)(m_prev + (size_t)row * MDIM + kb + kl);
                    }
                    As[(kl + 0) * 68 + row] = a.x; As[(kl + 1) * 68 + row] = a.y;
                    As[(kl + 2) * 68 + row] = a.z; As[(kl + 3) * 68 + row] = a.w;
                }
                {
                    int col = tid >> 2, kl = (tid & 3) << 2;
                    float4 v = *(const float4*)(Wmh + (size_t)(colBase + col) * MDIM + kb + kl);
                    Bs[(kl + 0) * 132 + col] = v.x; Bs[(kl + 1) * 132 + col] = v.y;
                    Bs[(kl + 2) * 132 + col] = v.z; Bs[(kl + 3) * 132 + col] = v.w;
                }
                __syncthreads();
                tile_compute44(As, Bs, ty, tx, acc);
                __syncthreads();
            }
#pragma unroll
            for (int r = 0; r < 4; r++) {
                float4 v = make_float4(((float2*)&acc[r][0])->x, ((float2*)&acc[r][0])->y,
                                       ((float2*)&acc[r][1])->x, ((float2*)&acc[r][1])->y);
                red_add_v4(g_c + (size_t)(ty * 4 + r) * HID + colBase + tx * 4, v);
            }
            sigrel(&cnt_c[ct4]);
        }

        // ====== stage 1b: bm-init out[t+1] active tiles (no deps) ======
        if (t + 1 < T_STEPS) {
            int kn = kval_d(t + 1);
            int j = bid - 120;
            if (j >= 0 && j < kn) {
                float* dst = out + (size_t)(t + 1) * BM;
                for (int idx = tid; idx < 4096; idx += NT) {
                    int row = idx >> 6, c4 = (idx & 63) << 2;
                    *(float4*)(dst + (size_t)row * MDIM + j * 256 + c4) =
                        *(const float4*)(bm + j * 256 + c4);
                }
                sigrel(&cnt_init[j]);
            }
        }

        // ====== stage 3: phase3 — red([m|h] @ [Wmm|Whm].T) into out[t] ======
        // h built inline: As for K>=MDIM is tanh(xh_t + c)
        {
            const int sp    = (kcur <= 2) ? 64 : (kcur <= 4 ? 32 : 16);
            const int units = (kcur == 1) ? 128 : kcur * sp;
            if (bid < units) {
                int ct256, colBase, s, Kc3;
                bool wide;
                if (kcur == 1) { wide = false; ct256 = 0; colBase = (bid >> 6) * 128; s = bid & 63; Kc3 = 48; }
                else           { wide = true;  ct256 = bid / sp; colBase = ct256 * 256; s = bid % sp; Kc3 = 3072 / sp; }
                const int kb0 = s * Kc3;
                // waits
#pragma unroll
                for (int j = 0; j < 8; j++)
                    if (j == ct256) waitge(&cnt_init[j], (unsigned)eI[j]);
                {
                    const int mk1 = min(kb0 + Kc3, MDIM);
                    if (t && mk1 > kb0) {
                        const int jlo = kb0 >> 8, jhi = (mk1 - 1) >> 8;
#pragma unroll
                        for (int j = 0; j < 8; j++)
                            if (j >= jlo && j <= jhi) waitge(&cnt_out[j], (unsigned)eo[j]);
                    }
                    const int hk0 = max(kb0, MDIM), hk1 = min(kb0 + Kc3, 3072);
                    if (hk1 > hk0) {   // c tiles (128-col) must be final for step t
                        const int jlo = (hk0 - MDIM) >> 7, jhi = (hk1 - 1 - MDIM) >> 7;
#pragma unroll
                        for (int j = 0; j < 8; j++)
                            if (j >= jlo && j <= jhi) waitge(&cnt_c[j], 16u * (unsigned)(t + 1));
                    }
                }
                unsigned long long acc[4][4];
#pragma unroll
                for (int r = 0; r < 4; r++)
#pragma unroll
                    for (int c = 0; c < 4; c++) acc[r][c] = 0ULL;

                const int chunks = Kc3 >> 4;
                for (int ch = 0; ch < chunks; ch++) {
                    int kb = kb0 + (ch << 4);
                    if (tid < 256) {
                        int row = tid >> 2, kl = (tid & 3) << 2;
                        float4 v;
                        if (kb < MDIM) {
                            v = __ldcg((const float4*)(mP + (size_t)row * MDIM + kb + kl));
                        } else {
                            size_t hoff = (size_t)row * HID + (kb - MDIM) + kl;
                            float4 cc = __ldcg((const float4*)(g_c + hoff));
                            float4 xx = *(const float4*)(g_xh + (size_t)t * BH + hoff);
                            v = make_float4(tanhf(xx.x + cc.x), tanhf(xx.y + cc.y),
                                            tanhf(xx.z + cc.z), tanhf(xx.w + cc.w));
                        }
                        As[(kl + 0) * 68 + row] = v.x; As[(kl + 1) * 68 + row] = v.y;
                        As[(kl + 2) * 68 + row] = v.z; As[(kl + 3) * 68 + row] = v.w;
                    }
                    if (wide) {
#pragma unroll
                        for (int i = 0; i < 2; i++) {
                            int g = tid + i * NT;
                            int col = g >> 2, kl = (g & 3) << 2;
                            int jg = colBase + col;
                            float4 v;
                            if (kb < MDIM) v = *(const float4*)(Wmm + (size_t)jg * MDIM + kb + kl);
                            else           v = *(const float4*)(Whm + (size_t)jg * HID + (kb - MDIM) + kl);
                            Bs[(kl + 0) * 260 + col] = v.x; Bs[(kl + 1) * 260 + col] = v.y;
                            Bs[(kl + 2) * 260 + col] = v.z; Bs[(kl + 3) * 260 + col] = v.w;
                        }
                    } else {
                        int col = tid >> 2, kl = (tid & 3) << 2;
                        int jg = colBase + col;
                        float4 v;
                        if (kb < MDIM) v = *(const float4*)(Wmm + (size_t)jg * MDIM + kb + kl);
                        else           v = *(const float4*)(Whm + (size_t)jg * HID + (kb - MDIM) + kl);
                        Bs[(kl + 0) * 132 + col] = v.x; Bs[(kl + 1) * 132 + col] = v.y;
                        Bs[(kl + 2) * 132 + col] = v.z; Bs[(kl + 3) * 132 + col] = v.w;
                    }
                    __syncthreads();
                    if (wide) tile_compute48(As, Bs, ty, tx, acc);
                    else      tile_compute44(As, Bs, ty, tx, (unsigned long long(*)[2])acc);
                    __syncthreads();
                }
                float* obase = out + (size_t)t * BM;
                if (wide) {
#pragma unroll
                    for (int r = 0; r < 4; r++) {
                        float2 a0 = *(float2*)&acc[r][0], a1 = *(float2*)&acc[r][1];
                        float2 a2 = *(float2*)&acc[r][2], a3 = *(float2*)&acc[r][3];
                        float* p = obase + (size_t)(ty * 4 + r) * MDIM + colBase + tx * 8;
                        red_add_v4(p,     make_float4(a0.x, a0.y, a1.x, a1.y));
                        red_add_v4(p + 4, make_float4(a2.x, a2.y, a3.x, a3.y));
                    }
                } else {
                    unsigned long long (*a2)[2] = (unsigned long long(*)[2])acc;
#pragma unroll
                    for (int r = 0; r < 4; r++) {
                        float2 a0 = *(float2*)&a2[r][0], a1 = *(float2*)&a2[r][1];
                        red_add_v4(obase + (size_t)(ty * 4 + r) * MDIM + colBase + tx * 4,
                                   make_float4(a0.x, a0.y, a1.x, a1.y));
                    }
                }
                sigrel(&cnt_out[ct256]);
            }
        }

        // ====== stage 4: copy inactive tiles (tiles >= kcur) ======
        {
            const int ct8 = bid >> 4, part = bid & 15;
            if (ct8 >= kcur) {
#pragma unroll
                for (int j = 0; j < 8; j++)
                    if (j == ct8) waitge(&cnt_out[j], (unsigned)eo[j]);
                const int row = tid >> 3;
                const int col = ct8 * 256 + part * 16 + (tid & 7) * 2;
                const size_t moff = (size_t)row * MDIM + col;
                float2 v = __ldcg((const float2*)(mP + moff));
                *(float2*)(out + (size_t)t * BM + moff) = v;
                sigrel(&cnt_out[ct8]);
            }
        }

        // ====== end-of-step bookkeeping ======
        {
            const int sp = (kcur <= 2) ? 64 : (kcur <= 4 ? 32 : 16);
            const int actsig = (kcur == 1) ? 128 : sp;
#pragma unroll
            for (int j = 0; j < 8; j++) eo[j] += (j < kcur) ? actsig : 16;
            if (t + 1 < T_STEPS) {
                int kn = kval_d(t + 1);
#pragma unroll
                for (int j = 0; j < 8; j++) if (j < kn) eI[j]++;
            }
        }
    }

    // ---- final: m_T = out[255] ----
#pragma unroll
    for (int j = 0; j < 8; j++) waitge(&cnt_out[j], (unsigned)eo[j]);
    {
        size_t o = (size_t)ft * 2;
        float2 v = __ldcg((const float2*)(out + (size_t)(T_STEPS - 1) * BM + o));
        *(float2*)(out + (size_t)T_STEPS * BM + o) = v;
    }
}

// ---------------- host ----------------
extern "C" void kernel_launch(void* const* d_in, const int* in_sizes, int n_in,
                              void* d_out, int out_size)
{
    const float* x      = (const float*)d_in[0];
    const float* m_prev = (const float*)d_in[1];
    const float* Wxh    = (const float*)d_in[2];
    const float* Whm    = (const float*)d_in[3];
    const float* Wmm    = (const float*)d_in[4];
    const float* Wmh    = (const float*)d_in[5];
    const float* bm     = (const float*)d_in[6];
    const float* bh     = (const float*)d_in[7];
    float* out = (float*)d_out;
    (void)in_sizes; (void)n_in; (void)out_size;

    xh_kernel<<<dim3(4, 256), 256>>>(x, Wxh, bh);
    rnn_persistent<<<NB, NT>>>(m_prev, Wmh, Wmm, Whm, bm, out);
}

// round 10
// speedup vs baseline: 2.3564x; 1.0455x over previous
#include <cuda_runtime.h>

#define T_STEPS 256
#define BATCH   64
#define IN_DIM  512
#define HID     1024
#define MDIM    2048
#define NB      128
#define NT      512
#define BM      (BATCH*MDIM)   // 131072
#define BH      (BATCH*HID)    // 65536

// ---------------- static device scratch ----------------
__device__ float g_xh[(size_t)T_STEPS * BH];  // x@Wxh + bh (64 MB)
__device__ float g_c[BH];                     // running c = m @ Wmh.T (red-accumulated)
__device__ unsigned g_cnt, g_gen;
__device__ unsigned cnt_c[8];     // per 128-col c tile: phase1 units done (16/step)
__device__ unsigned cnt_out[8];   // per 256-col out tile completion
__device__ unsigned cnt_init[8];  // per 256-col out tile bm-init events

// ---------------- packed fp32x2 ----------------
__device__ __forceinline__ unsigned long long pack2(float a) {
    unsigned long long r;
    asm("mov.b64 %0, {%1, %1};" : "=l"(r) : "f"(a));
    return r;
}
__device__ __forceinline__ void ffma2(unsigned long long& c, unsigned long long a, unsigned long long b) {
    asm("fma.rn.f32x2 %0, %1, %2, %0;" : "+l"(c) : "l"(a), "l"(b));
}

// ---------------- L2-side vector reduction ----------------
__device__ __forceinline__ void red_add_v4(float* p, float4 v) {
    asm volatile("red.global.add.v4.f32 [%0], {%1,%2,%3,%4};"
                 :: "l"(p), "f"(v.x), "f"(v.y), "f"(v.z), "f"(v.w) : "memory");
}

// ---------------- sync primitives ----------------
__device__ __forceinline__ unsigned ldacq(const unsigned* p) {
    unsigned v;
    asm volatile("ld.acquire.gpu.global.u32 %0, [%1];" : "=r"(v) : "l"(p) : "memory");
    return v;
}
__device__ __forceinline__ void waitge(const unsigned* c, unsigned tgt) {
    if (threadIdx.x == 0) { while (ldacq(c) < tgt) { } }
    __syncthreads();
}
__device__ __forceinline__ void sigrel(unsigned* c) {
    __threadfence();
    __syncthreads();
    if (threadIdx.x == 0) atomicAdd(c, 1u);
}
__device__ __forceinline__ void grid_barrier() {
    __threadfence();
    __syncthreads();
    if (threadIdx.x == 0) {
        volatile unsigned* vg = &g_gen;
        unsigned old = *vg;
        unsigned prev = atomicAdd(&g_cnt, 1u);
        if (prev == NB - 1) {
            atomicExch(&g_cnt, 0u);
            __threadfence();
            atomicAdd(&g_gen, 1u);
        } else {
            while (*vg == old) { __nanosleep(64); }
        }
    }
    __syncthreads();
}

__device__ __forceinline__ int kval_d(int t) { return t ? min(__ffs(t), 8) : 8; }

// ---------------- tile compute: 64 rows x 128 cols, 512 thr, 4x4 ----------
// As[k][row] stride 68; Bs[k][col] stride 260 (shared layout with wide mode)
__device__ __forceinline__ void tile_compute44(const float* As, const float* Bs,
                                               int ty, int tx, unsigned long long acc[4][2]) {
#pragma unroll
    for (int kk = 0; kk < 16; kk++) {
        float4 a = *(const float4*)(As + kk * 68 + ty * 4);
        const unsigned long long* bp = (const unsigned long long*)(Bs + kk * 260 + tx * 4);
        unsigned long long b0 = bp[0], b1 = bp[1];
        float as[4] = {a.x, a.y, a.z, a.w};
#pragma unroll
        for (int r = 0; r < 4; r++) {
            unsigned long long av = pack2(as[r]);
            ffma2(acc[r][0], av, b0);
            ffma2(acc[r][1], av, b1);
        }
    }
}
// ---------------- tile compute: 64 rows x 256 cols, 512 thr, 4x8 ----------
__device__ __forceinline__ void tile_compute48(const float* As, const float* Bs,
                                               int ty, int tx, unsigned long long acc[4][4]) {
#pragma unroll
    for (int kk = 0; kk < 16; kk++) {
        float4 a = *(const float4*)(As + kk * 68 + ty * 4);
        const unsigned long long* bp = (const unsigned long long*)(Bs + kk * 260 + tx * 8);
        unsigned long long b0 = bp[0], b1 = bp[1], b2 = bp[2], b3 = bp[3];
        float as[4] = {a.x, a.y, a.z, a.w};
#pragma unroll
        for (int r = 0; r < 4; r++) {
            unsigned long long av = pack2(as[r]);
            ffma2(acc[r][0], av, b0);
            ffma2(acc[r][1], av, b1);
            ffma2(acc[r][2], av, b2);
            ffma2(acc[r][3], av, b3);
        }
    }
}
// ---------------- 64x256, 256 thr, 8x8 (prologue only) ----------
__device__ __forceinline__ void tile_compute8(const float* As, const float* Bs,
                                              int ty, int tx, unsigned long long acc[8][4]) {
#pragma unroll
    for (int kk = 0; kk < 16; kk++) {
        float4 a0 = *(const float4*)(As + kk * 68 + ty * 8);
        float4 a1 = *(const float4*)(As + kk * 68 + ty * 8 + 4);
        const unsigned long long* bp = (const unsigned long long*)(Bs + kk * 260 + tx * 8);
        unsigned long long b0 = bp[0], b1 = bp[1], b2 = bp[2], b3 = bp[3];
        float as[8] = {a0.x, a0.y, a0.z, a0.w, a1.x, a1.y, a1.z, a1.w};
#pragma unroll
        for (int r = 0; r < 8; r++) {
            unsigned long long av = pack2(as[r]);
            ffma2(acc[r][0], av, b0);
            ffma2(acc[r][1], av, b1);
            ffma2(acc[r][2], av, b2);
            ffma2(acc[r][3], av, b3);
        }
    }
}

// ---------------- prologue: g_xh = x @ Wxh + bh ----------------
__global__ __launch_bounds__(256) void xh_kernel(
    const float* __restrict__ X, const float* __restrict__ Wxh, const float* __restrict__ bh)
{
    __shared__ float As[16 * 68];
    __shared__ float Bs[16 * 260];
    const int tid = threadIdx.x;
    const int ty = tid >> 5, tx = tid & 31;
    const int colBase = blockIdx.x * 256;
    const int rowBase = blockIdx.y * 64;

    unsigned long long acc[8][4];
#pragma unroll
    for (int r = 0; r < 8; r++)
#pragma unroll
        for (int c = 0; c < 4; c++) acc[r][c] = 0ULL;

    for (int ch = 0; ch < 32; ch++) {
        int kb = ch << 4;
        {
            int row = tid >> 2, kl = (tid & 3) << 2;
            float4 v = *(const float4*)(X + (size_t)(rowBase + row) * IN_DIM + kb + kl);
            As[(kl + 0) * 68 + row] = v.x; As[(kl + 1) * 68 + row] = v.y;
            As[(kl + 2) * 68 + row] = v.z; As[(kl + 3) * 68 + row] = v.w;
        }
#pragma unroll
        for (int i = 0; i < 4; i++) {
            int g = tid + i * 256;
            int kl = g >> 6, col4 = (g & 63) << 2;
            float4 v = *(const float4*)(Wxh + (size_t)(kb + kl) * HID + colBase + col4);
            *(float4*)(Bs + kl * 260 + col4) = v;
        }
        __syncthreads();
        tile_compute8(As, Bs, ty, tx, acc);
        __syncthreads();
    }
#pragma unroll
    for (int r = 0; r < 8; r++) {
        int row = rowBase + ty * 8 + r;
        int jg = colBase + tx * 8;
#pragma unroll
        for (int c = 0; c < 4; c++) {
            float2 v = *(float2*)&acc[r][c];
            float2 bb = *(const float2*)(bh + jg + c * 2);
            v.x += bb.x; v.y += bb.y;
            *(float2*)(g_xh + (size_t)row * HID + jg + c * 2) = v;
        }
    }
}

// ---------------- persistent dataflow recurrence ----------------
__global__ __launch_bounds__(NT, 1) void rnn_persistent(
    const float* __restrict__ m_prev, const float* __restrict__ Wmh,
    const float* __restrict__ Wmm, const float* __restrict__ Whm,
    const float* __restrict__ bm, float* __restrict__ out)
{
    __shared__ float As[2][16 * 68];
    __shared__ float Bs[2][16 * 260];
    const int tid = threadIdx.x;
    const int ty = tid >> 5, tx = tid & 31;
    const int bid = blockIdx.x;
    const int ft = bid * NT + tid;    // [0, 65536)

    // ---- startup: reset counters, zero g_c, bm-init out[0] ----
    if (bid == 0 && tid == 0) {
#pragma unroll
        for (int i = 0; i < 8; i++) { cnt_c[i] = 0; cnt_out[i] = 0; cnt_init[i] = 0; }
    }
    g_c[ft] = 0.0f;
    {   // out[0] = bm (all 8 tiles active at t=0)
        int col = (ft * 2) & (MDIM - 1);
        *(float2*)(out + (size_t)ft * 2) = *(const float2*)(bm + col);
    }
    grid_barrier();

    int eo[8];   // cnt_out totals through step t-1
    int eI[8];   // cnt_init totals scheduled through step t-1
#pragma unroll
    for (int j = 0; j < 8; j++) { eo[j] = 0; eI[j] = 0; }

    for (int t = 0; t < T_STEPS; t++) {
        const float* mP  = t ? (out + (size_t)(t - 1) * BM) : m_prev;
        const float* mPP = (t >= 2) ? (out + (size_t)(t - 2) * BM) : m_prev;
        const int kcur  = kval_d(t);
        const int kprev = (t <= 1) ? 8 : kval_d(t - 1);

        // ====== stage 1: phase1 — red(dm @ Wmh.T) into g_c (128 units) ======
        {
            const int ct4 = bid >> 4;          // 0..7 (128-col tile of HID)
            const int s   = bid & 15;          // split
            const int kb0 = s * (kprev << 4);
            // RAW (dm tiles) + WAR (all g_c readers of step t-1 signalled cnt_out
            // on active tiles j < kprev)
            if (t) {
#pragma unroll
                for (int j = 0; j < 8; j++)
                    if (j < kprev) waitge(&cnt_out[j], (unsigned)eo[j]);
            }
            unsigned long long acc[4][2];
#pragma unroll
            for (int r = 0; r < 4; r++) { acc[r][0] = 0ULL; acc[r][1] = 0ULL; }
            const int colBase = ct4 * 128;
            const int arow = tid >> 2, akl = (tid & 3) << 2;
            float4 aR = make_float4(0.f, 0.f, 0.f, 0.f);
            float4 bR = make_float4(0.f, 0.f, 0.f, 0.f);

#define P1_LOAD(CH) do { int kb = kb0 + ((CH) << 4);                                        \
    if (tid < 256) {                                                                        \
        if (t) {                                                                            \
            float4 p = __ldcg((const float4*)(mP  + (size_t)arow * MDIM + kb + akl));       \
            float4 q = __ldcg((const float4*)(mPP + (size_t)arow * MDIM + kb + akl));       \
            aR = make_float4(p.x - q.x, p.y - q.y, p.z - q.z, p.w - q.w);                   \
        } else {                                                                            \
            aR = *(const float4*)(m_prev + (size_t)arow * MDIM + kb + akl);                 \
        } }                                                                                 \
    bR = *(const float4*)(Wmh + (size_t)(colBase + arow) * MDIM + kb + akl);                \
} while (0)

#define P1_STORE(BF) do {                                                                   \
    if (tid < 256) {                                                                        \
        As[BF][(akl + 0) * 68 + arow] = aR.x; As[BF][(akl + 1) * 68 + arow] = aR.y;         \
        As[BF][(akl + 2) * 68 + arow] = aR.z; As[BF][(akl + 3) * 68 + arow] = aR.w; }       \
    Bs[BF][(akl + 0) * 260 + arow] = bR.x; Bs[BF][(akl + 1) * 260 + arow] = bR.y;           \
    Bs[BF][(akl + 2) * 260 + arow] = bR.z; Bs[BF][(akl + 3) * 260 + arow] = bR.w;           \
} while (0)

            P1_LOAD(0); P1_STORE(0); __syncthreads();
            for (int ch = 0; ch < kprev; ch++) {
                if (ch + 1 < kprev) P1_LOAD(ch + 1);
                tile_compute44(As[ch & 1], Bs[ch & 1], ty, tx, acc);
                if (ch + 1 < kprev) { P1_STORE((ch + 1) & 1); __syncthreads(); }
            }
#pragma unroll
            for (int r = 0; r < 4; r++) {
                float4 v = make_float4(((float2*)&acc[r][0])->x, ((float2*)&acc[r][0])->y,
                                       ((float2*)&acc[r][1])->x, ((float2*)&acc[r][1])->y);
                red_add_v4(g_c + (size_t)(ty * 4 + r) * HID + colBase + tx * 4, v);
            }
            sigrel(&cnt_c[ct4]);
        }

        // ====== stage 1b: bm-init out[t+1] active tiles (no deps) ======
        if (t + 1 < T_STEPS) {
            int kn = kval_d(t + 1);
            int j = bid - 120;
            if (j >= 0 && j < kn) {
                float* dst = out + (size_t)(t + 1) * BM;
                for (int idx = tid; idx < 4096; idx += NT) {
                    int row = idx >> 6, c4 = (idx & 63) << 2;
                    *(float4*)(dst + (size_t)row * MDIM + j * 256 + c4) =
                        *(const float4*)(bm + j * 256 + c4);
                }
                sigrel(&cnt_init[j]);
            }
        }

        // ====== stage 3: phase3 — red([m|h] @ [Wmm|Whm].T) into out[t] ======
        // h built inline: A-tile for K>=MDIM is tanh(xh_t + c)
        {
            const int sp    = (kcur <= 2) ? 64 : (kcur <= 4 ? 32 : 16);
            const int units = (kcur == 1) ? 128 : kcur * sp;
            if (bid < units) {
                int ct256, colBase, s, Kc3;
                bool wide;
                if (kcur == 1) { wide = false; ct256 = 0; colBase = (bid >> 6) * 128; s = bid & 63; Kc3 = 48; }
                else           { wide = true;  ct256 = bid / sp; colBase = ct256 * 256; s = bid % sp; Kc3 = 3072 / sp; }
                const int kb0 = s * Kc3;
                // waits
#pragma unroll
                for (int j = 0; j < 8; j++)
                    if (j == ct256) waitge(&cnt_init[j], (unsigned)eI[j]);
                {
                    const int mk1 = min(kb0 + Kc3, MDIM);
                    if (t && mk1 > kb0) {
                        const int jlo = kb0 >> 8, jhi = (mk1 - 1) >> 8;
#pragma unroll
                        for (int j = 0; j < 8; j++)
                            if (j >= jlo && j <= jhi) waitge(&cnt_out[j], (unsigned)eo[j]);
                    }
                    const int hk0 = max(kb0, MDIM), hk1 = min(kb0 + Kc3, 3072);
                    if (hk1 > hk0) {   // c tiles (128-col) must be final for step t
                        const int jlo = (hk0 - MDIM) >> 7, jhi = (hk1 - 1 - MDIM) >> 7;
#pragma unroll
                        for (int j = 0; j < 8; j++)
                            if (j >= jlo && j <= jhi) waitge(&cnt_c[j], 16u * (unsigned)(t + 1));
                    }
                }
                unsigned long long acc[4][4];
#pragma unroll
                for (int r = 0; r < 4; r++)
#pragma unroll
                    for (int c = 0; c < 4; c++) acc[r][c] = 0ULL;

                const int chunks = Kc3 >> 4;
                const int arow = tid >> 2, akl = (tid & 3) << 2;
                float4 aR  = make_float4(0.f, 0.f, 0.f, 0.f);
                float4 bR0 = make_float4(0.f, 0.f, 0.f, 0.f);
                float4 bR1 = make_float4(0.f, 0.f, 0.f, 0.f);

#define P3_LOAD(CH) do { int kb = kb0 + ((CH) << 4);                                        \
    if (tid < 256) {                                                                        \
        if (kb < MDIM) {                                                                    \
            aR = __ldcg((const float4*)(mP + (size_t)arow * MDIM + kb + akl));              \
        } else {                                                                            \
            size_t hoff = (size_t)arow * HID + (kb - MDIM) + akl;                           \
            float4 cc = __ldcg((const float4*)(g_c + hoff));                                \
            float4 xx = *(const float4*)(g_xh + (size_t)t * BH + hoff);                     \
            aR = make_float4(tanhf(xx.x + cc.x), tanhf(xx.y + cc.y),                        \
                             tanhf(xx.z + cc.z), tanhf(xx.w + cc.w));                       \
        } }                                                                                 \
    { int jg = colBase + arow;                                                              \
      bR0 = (kb < MDIM) ? *(const float4*)(Wmm + (size_t)jg * MDIM + kb + akl)              \
                        : *(const float4*)(Whm + (size_t)jg * HID + (kb - MDIM) + akl); }   \
    if (wide) { int jg = colBase + 128 + arow;                                              \
      bR1 = (kb < MDIM) ? *(const float4*)(Wmm + (size_t)jg * MDIM + kb + akl)              \
                        : *(const float4*)(Whm + (size_t)jg * HID + (kb - MDIM) + akl); }   \
} while (0)

#define P3_STORE(BF) do {                                                                   \
    if (tid < 256) {                                                                        \
        As[BF][(akl + 0) * 68 + arow] = aR.x; As[BF][(akl + 1) * 68 + arow] = aR.y;         \
        As[BF][(akl + 2) * 68 + arow] = aR.z; As[BF][(akl + 3) * 68 + arow] = aR.w; }       \
    Bs[BF][(akl + 0) * 260 + arow] = bR0.x; Bs[BF][(akl + 1) * 260 + arow] = bR0.y;         \
    Bs[BF][(akl + 2) * 260 + arow] = bR0.z; Bs[BF][(akl + 3) * 260 + arow] = bR0.w;         \
    if (wide) { int c2 = arow + 128;                                                        \
        Bs[BF][(akl + 0) * 260 + c2] = bR1.x; Bs[BF][(akl + 1) * 260 + c2] = bR1.y;         \
        Bs[BF][(akl + 2) * 260 + c2] = bR1.z; Bs[BF][(akl + 3) * 260 + c2] = bR1.w; }       \
} while (0)

                P3_LOAD(0); P3_STORE(0); __syncthreads();
                for (int ch = 0; ch < chunks; ch++) {
                    if (ch + 1 < chunks) P3_LOAD(ch + 1);
                    if (wide) tile_compute48(As[ch & 1], Bs[ch & 1], ty, tx, acc);
                    else      tile_compute44(As[ch & 1], Bs[ch & 1], ty, tx, (unsigned long long(*)[2])acc);
                    if (ch + 1 < chunks) { P3_STORE((ch + 1) & 1); __syncthreads(); }
                }
                float* obase = out + (size_t)t * BM;
                if (wide) {
#pragma unroll
                    for (int r = 0; r < 4; r++) {
                        float2 a0 = *(float2*)&acc[r][0], a1 = *(float2*)&acc[r][1];
                        float2 a2 = *(float2*)&acc[r][2], a3 = *(float2*)&acc[r][3];
                        float* p = obase + (size_t)(ty * 4 + r) * MDIM + colBase + tx * 8;
                        red_add_v4(p,     make_float4(a0.x, a0.y, a1.x, a1.y));
                        red_add_v4(p + 4, make_float4(a2.x, a2.y, a3.x, a3.y));
                    }
                } else {
                    unsigned long long (*a2)[2] = (unsigned long long(*)[2])acc;
#pragma unroll
                    for (int r = 0; r < 4; r++) {
                        float2 a0 = *(float2*)&a2[r][0], a1 = *(float2*)&a2[r][1];
                        red_add_v4(obase + (size_t)(ty * 4 + r) * MDIM + colBase + tx * 4,
                                   make_float4(a0.x, a0.y, a1.x, a1.y));
                    }
                }
                sigrel(&cnt_out[ct256]);
            }
        }

        // ====== stage 4: copy inactive tiles (tiles >= kcur) ======
        {
            const int ct8 = bid >> 4, part = bid & 15;
            if (ct8 >= kcur) {
#pragma unroll
                for (int j = 0; j < 8; j++)
                    if (j == ct8) waitge(&cnt_out[j], (unsigned)eo[j]);
                const int row = tid >> 3;
                const int col = ct8 * 256 + part * 16 + (tid & 7) * 2;
                const size_t moff = (size_t)row * MDIM + col;
                float2 v = __ldcg((const float2*)(mP + moff));
                *(float2*)(out + (size_t)t * BM + moff) = v;
                sigrel(&cnt_out[ct8]);
            }
        }

        // ====== end-of-step bookkeeping ======
        {
            const int sp = (kcur <= 2) ? 64 : (kcur <= 4 ? 32 : 16);
            const int actsig = (kcur == 1) ? 128 : sp;
#pragma unroll
            for (int j = 0; j < 8; j++) eo[j] += (j < kcur) ? actsig : 16;
            if (t + 1 < T_STEPS) {
                int kn = kval_d(t + 1);
#pragma unroll
                for (int j = 0; j < 8; j++) if (j < kn) eI[j]++;
            }
        }
    }

    // ---- final: m_T = out[255] ----
#pragma unroll
    for (int j = 0; j < 8; j++) waitge(&cnt_out[j], (unsigned)eo[j]);
    {
        size_t o = (size_t)ft * 2;
        float2 v = __ldcg((const float2*)(out + (size_t)(T_STEPS - 1) * BM + o));
        *(float2*)(out + (size_t)T_STEPS * BM + o) = v;
    }
}

// ---------------- host ----------------
extern "C" void kernel_launch(void* const* d_in, const int* in_sizes, int n_in,
                              void* d_out, int out_size)
{
    const float* x      = (const float*)d_in[0];
    const float* m_prev = (const float*)d_in[1];
    const float* Wxh    = (const float*)d_in[2];
    const float* Whm    = (const float*)d_in[3];
    const float* Wmm    = (const float*)d_in[4];
    const float* Wmh    = (const float*)d_in[5];
    const float* bm     = (const float*)d_in[6];
    const float* bh     = (const float*)d_in[7];
    float* out = (float*)d_out;
    (void)in_sizes; (void)n_in; (void)out_size;

    xh_kernel<<<dim3(4, 256), 256>>>(x, Wxh, bh);
    rnn_persistent<<<NB, NT>>>(m_prev, Wmh, Wmm, Whm, bm, out);
}

// round 13
// speedup vs baseline: 2.6547x; 1.1266x over previous
#include <cuda_runtime.h>

#define T_STEPS 256
#define BATCH   64
#define IN_DIM  512
#define HID     1024
#define MDIM    2048
#define NB      128
#define NTF     512
#define BM      (BATCH*MDIM)   // 131072
#define BH      (BATCH*HID)    // 65536
#define AS_STR  68
#define BS_STR  132
#define AS_SZ   (16*AS_STR)    // 1088 floats
#define BS_SZ   (16*BS_STR)    // 2112 floats
#define SMEM_FLOATS (4*AS_SZ + 4*BS_SZ)   // 12800 floats = 51200 B

// ---------------- static device scratch ----------------
__device__ float g_xh[(size_t)T_STEPS * BH];  // x@Wxh + bh (64 MB)
__device__ float g_c[BH];                     // running c = m @ Wmh.T (red-accumulated)
__device__ unsigned g_cnt, g_gen;
__device__ unsigned cnt_c[8];     // per 128-col c tile: phase1 units done (16/step)
__device__ unsigned cnt_out[8];   // per 256-col out tile completion (step-ordered!)
__device__ unsigned cnt_init[8];  // per 256-col out tile bm-init events (single signaller)

// ---------------- packed fp32x2 ----------------
__device__ __forceinline__ unsigned long long pack2(float a) {
    unsigned long long r;
    asm("mov.b64 %0, {%1, %1};" : "=l"(r) : "f"(a));
    return r;
}
__device__ __forceinline__ void ffma2(unsigned long long& c, unsigned long long a, unsigned long long b) {
    asm("fma.rn.f32x2 %0, %1, %2, %0;" : "+l"(c) : "l"(a), "l"(b));
}

// ---------------- L2-side vector reduction ----------------
__device__ __forceinline__ void red_add_v4(float* p, float4 v) {
    asm volatile("red.global.add.v4.f32 [%0], {%1,%2,%3,%4};"
                 :: "l"(p), "f"(v.x), "f"(v.y), "f"(v.z), "f"(v.w) : "memory");
}

// ---------------- sync primitives ----------------
__device__ __forceinline__ unsigned ldacq(const unsigned* p) {
    unsigned v;
    asm volatile("ld.acquire.gpu.global.u32 %0, [%1];" : "=r"(v) : "l"(p) : "memory");
    return v;
}
__device__ __forceinline__ void halfbar(int id) {
    asm volatile("bar.sync %0, %1;" :: "r"(id), "r"(256) : "memory");
}
__device__ __forceinline__ void waitge_h(const unsigned* c, unsigned tgt, int id, bool lead) {
    if (lead) { while (ldacq(c) < tgt) { } }
    halfbar(id);
}
__device__ __forceinline__ void sigrel_h(unsigned* c, int id, bool lead) {
    __threadfence();
    halfbar(id);
    if (lead) atomicAdd(c, 1u);
}
__device__ __forceinline__ void grid_barrier() {
    __threadfence();
    __syncthreads();
    if (threadIdx.x == 0) {
        volatile unsigned* vg = &g_gen;
        unsigned old = *vg;
        unsigned prev = atomicAdd(&g_cnt, 1u);
        if (prev == NB - 1) {
            atomicExch(&g_cnt, 0u);
            __threadfence();
            atomicAdd(&g_gen, 1u);
        } else {
            while (*vg == old) { __nanosleep(64); }
        }
    }
    __syncthreads();
}

__device__ __forceinline__ int kval_d(int t) { return t ? min(__ffs(t), 8) : 8; }
// exact split table: sp3*Kc3 == 3072, units = 2*kcur*sp3 <= 128
__device__ __forceinline__ int sp3_of(int k) {
    return (k == 1) ? 64 : (k == 2) ? 32 : (k <= 4) ? 16 : (k == 5) ? 12 : 8;
}

// ---------------- tile compute: 64 rows x 128 cols, 256 thr, 8x4 ----------
__device__ __forceinline__ void tile82(const float* As, const float* Bs,
                                       int ty, int tx, unsigned long long acc[8][2]) {
#pragma unroll
    for (int kk = 0; kk < 16; kk++) {
        float4 a0 = *(const float4*)(As + kk * AS_STR + ty * 8);
        float4 a1 = *(const float4*)(As + kk * AS_STR + ty * 8 + 4);
        const unsigned long long* bp = (const unsigned long long*)(Bs + kk * BS_STR + tx * 4);
        unsigned long long b0 = bp[0], b1 = bp[1];
        float as[8] = {a0.x, a0.y, a0.z, a0.w, a1.x, a1.y, a1.z, a1.w};
#pragma unroll
        for (int r = 0; r < 8; r++) {
            unsigned long long av = pack2(as[r]);
            ffma2(acc[r][0], av, b0);
            ffma2(acc[r][1], av, b1);
        }
    }
}
// ---------------- 64x256, 256 thr, 8x8 (prologue only) ----------
__device__ __forceinline__ void tile_compute8(const float* As, const float* Bs,
                                              int ty, int tx, unsigned long long acc[8][4]) {
#pragma unroll
    for (int kk = 0; kk < 16; kk++) {
        float4 a0 = *(const float4*)(As + kk * 68 + ty * 8);
        float4 a1 = *(const float4*)(As + kk * 68 + ty * 8 + 4);
        const unsigned long long* bp = (const unsigned long long*)(Bs + kk * 260 + tx * 8);
        unsigned long long b0 = bp[0], b1 = bp[1], b2 = bp[2], b3 = bp[3];
        float as[8] = {a0.x, a0.y, a0.z, a0.w, a1.x, a1.y, a1.z, a1.w};
#pragma unroll
        for (int r = 0; r < 8; r++) {
            unsigned long long av = pack2(as[r]);
            ffma2(acc[r][0], av, b0);
            ffma2(acc[r][1], av, b1);
            ffma2(acc[r][2], av, b2);
            ffma2(acc[r][3], av, b3);
        }
    }
}

// ---------------- prologue: g_xh = x @ Wxh + bh ----------------
__global__ __launch_bounds__(256) void xh_kernel(
    const float* __restrict__ X, const float* __restrict__ Wxh, const float* __restrict__ bh)
{
    __shared__ float As[16 * 68];
    __shared__ float Bs[16 * 260];
    const int tid = threadIdx.x;
    const int ty = tid >> 5, tx = tid & 31;
    const int colBase = blockIdx.x * 256;
    const int rowBase = blockIdx.y * 64;

    unsigned long long acc[8][4];
#pragma unroll
    for (int r = 0; r < 8; r++)
#pragma unroll
        for (int c = 0; c < 4; c++) acc[r][c] = 0ULL;

    for (int ch = 0; ch < 32; ch++) {
        int kb = ch << 4;
        {
            int row = tid >> 2, kl = (tid & 3) << 2;
            float4 v = *(const float4*)(X + (size_t)(rowBase + row) * IN_DIM + kb + kl);
            As[(kl + 0) * 68 + row] = v.x; As[(kl + 1) * 68 + row] = v.y;
            As[(kl + 2) * 68 + row] = v.z; As[(kl + 3) * 68 + row] = v.w;
        }
#pragma unroll
        for (int i = 0; i < 4; i++) {
            int g = tid + i * 256;
            int kl = g >> 6, col4 = (g & 63) << 2;
            float4 v = *(const float4*)(Wxh + (size_t)(kb + kl) * HID + colBase + col4);
            *(float4*)(Bs + kl * 260 + col4) = v;
        }
        __syncthreads();
        tile_compute8(As, Bs, ty, tx, acc);
        __syncthreads();
    }
#pragma unroll
    for (int r = 0; r < 8; r++) {
        int row = rowBase + ty * 8 + r;
        int jg = colBase + tx * 8;
#pragma unroll
        for (int c = 0; c < 4; c++) {
            float2 v = *(float2*)&acc[r][c];
            float2 bb = *(const float2*)(bh + jg + c * 2);
            v.x += bb.x; v.y += bb.y;
            *(float2*)(g_xh + (size_t)row * HID + jg + c * 2) = v;
        }
    }
}

// ---------------- persistent dataflow recurrence (warp-specialized halves) ----
__global__ __launch_bounds__(NTF, 1) void rnn_persistent(
    const float* __restrict__ m_prev, const float* __restrict__ Wmh,
    const float* __restrict__ Wmm, const float* __restrict__ Whm,
    const float* __restrict__ bm, float* __restrict__ out)
{
    extern __shared__ float sm[];
    float* AsA = sm;
    float* BsA = sm + 2 * AS_SZ;
    float* AsB = sm + 2 * AS_SZ + 2 * BS_SZ;
    float* BsB = AsB + 2 * AS_SZ;

    const int tid = threadIdx.x;
    const int bid = blockIdx.x;

    // ---- startup (full block): reset counters, zero g_c, out[0]=bm ----
    if (bid == 0 && tid == 0) {
#pragma unroll
        for (int i = 0; i < 8; i++) { cnt_c[i] = 0; cnt_out[i] = 0; cnt_init[i] = 0; }
    }
    {
        int ft = bid * NTF + tid;          // [0, 65536)
        g_c[ft] = 0.0f;
        int col = (ft * 2) & (MDIM - 1);
        *(float2*)(out + (size_t)ft * 2) = *(const float2*)(bm + col);
    }
    grid_barrier();

    if (tid < 256) {
        // ================= HALF A: phase1 + bm-init + copies =================
        const int l = tid;
        const bool lead = (l == 0);
        const int ty = l >> 5, tx = l & 31;
        const int arow = l >> 2, akl = (l & 3) << 2;
        int eo[8];
#pragma unroll
        for (int j = 0; j < 8; j++) eo[j] = 0;

        for (int t = 0; t < T_STEPS; t++) {
            const float* mP  = t ? (out + (size_t)(t - 1) * BM) : m_prev;
            const float* mPP = (t >= 2) ? (out + (size_t)(t - 2) * BM) : m_prev;
            const int kcur  = kval_d(t);
            const int kprev = (t <= 1) ? 8 : kval_d(t - 1);

            // ---- phase1: red(dm @ Wmh.T) into g_c ----
            {
                const int ct4 = bid >> 4, s = bid & 15;
                const int kb0 = s * (kprev << 4);
                const int colBase = ct4 * 128;
                if (t) {
#pragma unroll
                    for (int j = 0; j < 8; j++)
                        if (j < kprev) waitge_h(&cnt_out[j], (unsigned)eo[j], 1, lead);
                }
                unsigned long long acc[8][2];
#pragma unroll
                for (int r = 0; r < 8; r++) { acc[r][0] = 0ULL; acc[r][1] = 0ULL; }
                float4 aR = make_float4(0.f,0.f,0.f,0.f);
                float4 bR0 = aR, bR1 = aR;

#define P1_LOAD(CH) do { int kb = kb0 + ((CH) << 4);                                       \
    if (t) {                                                                               \
        float4 p = __ldcg((const float4*)(mP  + (size_t)arow * MDIM + kb + akl));          \
        float4 q = __ldcg((const float4*)(mPP + (size_t)arow * MDIM + kb + akl));          \
        aR = make_float4(p.x - q.x, p.y - q.y, p.z - q.z, p.w - q.w);                      \
    } else {                                                                               \
        aR = *(const float4*)(m_prev + (size_t)arow * MDIM + kb + akl);                    \
    }                                                                                      \
    bR0 = *(const float4*)(Wmh + (size_t)(colBase + arow) * MDIM + kb + akl);              \
    bR1 = *(const float4*)(Wmh + (size_t)(colBase + 64 + arow) * MDIM + kb + akl);         \
} while (0)

#define P1_STORE(BF) do { float* A_ = AsA + (BF) * AS_SZ; float* B_ = BsA + (BF) * BS_SZ;  \
    A_[(akl + 0) * AS_STR + arow] = aR.x; A_[(akl + 1) * AS_STR + arow] = aR.y;            \
    A_[(akl + 2) * AS_STR + arow] = aR.z; A_[(akl + 3) * AS_STR + arow] = aR.w;            \
    B_[(akl + 0) * BS_STR + arow] = bR0.x; B_[(akl + 1) * BS_STR + arow] = bR0.y;          \
    B_[(akl + 2) * BS_STR + arow] = bR0.z; B_[(akl + 3) * BS_STR + arow] = bR0.w;          \
    B_[(akl + 0) * BS_STR + 64 + arow] = bR1.x; B_[(akl + 1) * BS_STR + 64 + arow] = bR1.y;\
    B_[(akl + 2) * BS_STR + 64 + arow] = bR1.z; B_[(akl + 3) * BS_STR + 64 + arow] = bR1.w;\
} while (0)

                P1_LOAD(0); P1_STORE(0); halfbar(1);
                for (int ch = 0; ch < kprev; ch++) {
                    if (ch + 1 < kprev) P1_LOAD(ch + 1);
                    tile82(AsA + (ch & 1) * AS_SZ, BsA + (ch & 1) * BS_SZ, ty, tx, acc);
                    if (ch + 1 < kprev) { P1_STORE((ch + 1) & 1); halfbar(1); }
                }
#pragma unroll
                for (int r = 0; r < 8; r++) {
                    float2 a0 = *(float2*)&acc[r][0], a1 = *(float2*)&acc[r][1];
                    red_add_v4(g_c + (size_t)(ty * 8 + r) * HID + colBase + tx * 4,
                               make_float4(a0.x, a0.y, a1.x, a1.y));
                }
                sigrel_h(&cnt_c[ct4], 1, lead);
            }

            // ---- bm-init out[t+1] active tiles ----
            if (t + 1 < T_STEPS) {
                int kn = kval_d(t + 1);
                int j = bid - 120;
                if (j >= 0 && j < kn) {
                    float* dst = out + (size_t)(t + 1) * BM;
                    for (int idx = l; idx < 4096; idx += 256) {
                        int row = idx >> 6, c4 = (idx & 63) << 2;
                        *(float4*)(dst + (size_t)row * MDIM + j * 256 + c4) =
                            *(const float4*)(bm + j * 256 + c4);
                    }
                    sigrel_h(&cnt_init[j], 1, lead);
                }
            }

            // ---- copies: inactive tiles (wait = RAW + signal ordering) ----
            {
                const int ct8 = bid >> 4, part = bid & 15;
                if (ct8 >= kcur) {
                    waitge_h(&cnt_out[ct8], (unsigned)eo[ct8], 1, lead);
                    int row = l >> 2;
                    int col = ct8 * 256 + part * 16 + (l & 3) * 4;
                    size_t moff = (size_t)row * MDIM + col;
                    float4 v = __ldcg((const float4*)(mP + moff));
                    *(float4*)(out + (size_t)t * BM + moff) = v;
                    sigrel_h(&cnt_out[ct8], 1, lead);
                }
            }

            // ---- bookkeeping ----
            {
                const int as = 2 * sp3_of(kcur);
#pragma unroll
                for (int j = 0; j < 8; j++) eo[j] += (j < kcur) ? as : 16;
            }
        }

        // ---- final: m_T = out[255] ----
#pragma unroll
        for (int j = 0; j < 8; j++) waitge_h(&cnt_out[j], (unsigned)eo[j], 1, lead);
        {
            int ft2 = bid * 256 + l;      // [0, 32768)
            float4 v = __ldcg((const float4*)(out + (size_t)(T_STEPS - 1) * BM + (size_t)ft2 * 4));
            *(float4*)(out + (size_t)T_STEPS * BM + (size_t)ft2 * 4) = v;
        }
    } else {
        // ================= HALF B: phase3 =================
        const int l = tid - 256;
        const bool lead = (l == 0);
        const int ty = l >> 5, tx = l & 31;
        const int arow = l >> 2, akl = (l & 3) << 2;
        int eo[8], eI[8];
#pragma unroll
        for (int j = 0; j < 8; j++) { eo[j] = 0; eI[j] = 0; }

        for (int t = 0; t < T_STEPS; t++) {
            const float* mP = t ? (out + (size_t)(t - 1) * BM) : m_prev;
            const int kcur = kval_d(t);
            const int sp3 = sp3_of(kcur);
            const int units = 2 * kcur * sp3;        // <= 128, exact
            if (bid < units) {
                const int Kc3 = 3072 / sp3;          // multiple of 16 by table
                const int chunks = Kc3 >> 4;
                const int t128 = bid / sp3;          // 128-col tile, in range
                const int s = bid - t128 * sp3;
                const int colBase = t128 * 128;
                const int ct256 = t128 >> 1;
                const int kb0 = s * Kc3;
                const int kend = kb0 + Kc3;

                waitge_h(&cnt_init[ct256], (unsigned)eI[ct256], 2, lead);
                {   // m-region RAW waits
                    const int mk1 = min(kend, MDIM);
                    if (t && mk1 > kb0) {
                        const int jlo = kb0 >> 8, jhi = (mk1 - 1) >> 8;
#pragma unroll
                        for (int j = 0; j < 8; j++)
                            if (j >= jlo && j <= jhi) waitge_h(&cnt_out[j], (unsigned)eo[j], 2, lead);
                    }
                }
                // deferred c-region wait boundary
                const int hstart = (kb0 >= MDIM) ? 0 : ((kend <= MDIM) ? chunks : ((MDIM - kb0) >> 4));

#define P3_CWAITS() do {                                                                   \
    const int hk0 = (kb0 > MDIM) ? kb0 : MDIM;                                             \
    const int jlo = (hk0 - MDIM) >> 7, jhi = (kend - 1 - MDIM) >> 7;                       \
    _Pragma("unroll")                                                                      \
    for (int j = 0; j < 8; j++)                                                            \
        if (j >= jlo && j <= jhi) waitge_h(&cnt_c[j], 16u * (unsigned)(t + 1), 2, lead);   \
} while (0)

                unsigned long long acc[8][2];
#pragma unroll
                for (int r = 0; r < 8; r++) { acc[r][0] = 0ULL; acc[r][1] = 0ULL; }
                float4 aR = make_float4(0.f,0.f,0.f,0.f);
                float4 bR0 = aR, bR1 = aR;

#define P3_LOAD(CH) do { int kb = kb0 + ((CH) << 4);                                       \
    if (kb < MDIM) {                                                                       \
        aR = __ldcg((const float4*)(mP + (size_t)arow * MDIM + kb + akl));                 \
    } else {                                                                               \
        size_t hoff = (size_t)arow * HID + (kb - MDIM) + akl;                              \
        float4 cc = __ldcg((const float4*)(g_c + hoff));                                   \
        float4 xx = *(const float4*)(g_xh + (size_t)t * BH + hoff);                        \
        aR = make_float4(tanhf(xx.x + cc.x), tanhf(xx.y + cc.y),                           \
                         tanhf(xx.z + cc.z), tanhf(xx.w + cc.w));                          \
    }                                                                                      \
    { int jg = colBase + arow;                                                             \
      bR0 = (kb < MDIM) ? *(const float4*)(Wmm + (size_t)jg * MDIM + kb + akl)             \
                        : *(const float4*)(Whm + (size_t)jg * HID + (kb - MDIM) + akl); }  \
    { int jg = colBase + 64 + arow;                                                        \
      bR1 = (kb < MDIM) ? *(const float4*)(Wmm + (size_t)jg * MDIM + kb + akl)             \
                        : *(const float4*)(Whm + (size_t)jg * HID + (kb - MDIM) + akl); }  \
} while (0)

#define P3_STORE(BF) do { float* A_ = AsB + (BF) * AS_SZ; float* B_ = BsB + (BF) * BS_SZ;  \
    A_[(akl + 0) * AS_STR + arow] = aR.x; A_[(akl + 1) * AS_STR + arow] = aR.y;            \
    A_[(akl + 2) * AS_STR + arow] = aR.z; A_[(akl + 3) * AS_STR + arow] = aR.w;            \
    B_[(akl + 0) * BS_STR + arow] = bR0.x; B_[(akl + 1) * BS_STR + arow] = bR0.y;          \
    B_[(akl + 2) * BS_STR + arow] = bR0.z; B_[(akl + 3) * BS_STR + arow] = bR0.w;          \
    B_[(akl + 0) * BS_STR + 64 + arow] = bR1.x; B_[(akl + 1) * BS_STR + 64 + arow] = bR1.y;\
    B_[(akl + 2) * BS_STR + 64 + arow] = bR1.z; B_[(akl + 3) * BS_STR + 64 + arow] = bR1.w;\
} while (0)

                if (hstart == 0) P3_CWAITS();
                P3_LOAD(0); P3_STORE(0); halfbar(2);
                for (int ch = 0; ch < chunks; ch++) {
                    if (ch + 1 < chunks) {
                        if (ch + 1 == hstart) P3_CWAITS();
                        P3_LOAD(ch + 1);
                    }
                    tile82(AsB + (ch & 1) * AS_SZ, BsB + (ch & 1) * BS_SZ, ty, tx, acc);
                    if (ch + 1 < chunks) { P3_STORE((ch + 1) & 1); halfbar(2); }
                }
                {
                    float* obase = out + (size_t)t * BM;
#pragma unroll
                    for (int r = 0; r < 8; r++) {
                        float2 a0 = *(float2*)&acc[r][0], a1 = *(float2*)&acc[r][1];
                        red_add_v4(obase + (size_t)(ty * 8 + r) * MDIM + colBase + tx * 4,
                                   make_float4(a0.x, a0.y, a1.x, a1.y));
                    }
                }
                // signal-ordering wait: no step-t signal may land on cnt_out[ct256]
                // before all step<=t-1 signals (keeps cumulative counts step-ordered;
                // placed after the reds so it overlaps the GEMM, not the signal path)
                waitge_h(&cnt_out[ct256], (unsigned)eo[ct256], 2, lead);
                sigrel_h(&cnt_out[ct256], 2, lead);
            }

            // ---- bookkeeping ----
            {
                const int as = 2 * sp3;
#pragma unroll
                for (int j = 0; j < 8; j++) eo[j] += (j < kcur) ? as : 16;
            }
            if (t + 1 < T_STEPS) {
                int kn = kval_d(t + 1);
#pragma unroll
                for (int j = 0; j < 8; j++) if (j < kn) eI[j]++;
            }
        }
    }
}

// ---------------- host ----------------
extern "C" void kernel_launch(void* const* d_in, const int* in_sizes, int n_in,
                              void* d_out, int out_size)
{
    const float* x      = (const float*)d_in[0];
    const float* m_prev = (const float*)d_in[1];
    const float* Wxh    = (const float*)d_in[2];
    const float* Whm    = (const float*)d_in[3];
    const float* Wmm    = (const float*)d_in[4];
    const float* Wmh    = (const float*)d_in[5];
    const float* bm     = (const float*)d_in[6];
    const float* bh     = (const float*)d_in[7];
    float* out = (float*)d_out;
    (void)in_sizes; (void)n_in; (void)out_size;

    cudaFuncSetAttribute(rnn_persistent,
                         cudaFuncAttributeMaxDynamicSharedMemorySize,
                         SMEM_FLOATS * sizeof(float));

    xh_kernel<<<dim3(4, 256), 256>>>(x, Wxh, bh);
    rnn_persistent<<<NB, NTF, SMEM_FLOATS * sizeof(float)>>>(m_prev, Wmh, Wmm, Whm, bm, out);
}

// round 14
// speedup vs baseline: 3.0459x; 1.1474x over previous
#include <cuda_runtime.h>

#define T_STEPS 256
#define BATCH   64
#define IN_DIM  512
#define HID     1024
#define MDIM    2048
#define NB      128
#define NTF     512
#define BM      (BATCH*MDIM)   // 131072
#define BH      (BATCH*HID)    // 65536
#define AS_STR  68
#define BS_STR  132
#define AS_SZ   (16*AS_STR)    // 1088 floats
#define BS_SZ   (16*BS_STR)    // 2112 floats
#define SMEM_FLOATS (4*AS_SZ + 4*BS_SZ)   // 12800 floats = 51200 B

// ---------------- static device scratch ----------------
__device__ float g_xh[(size_t)T_STEPS * BH];  // x@Wxh + bh (64 MB)
__device__ float g_c[BH];                     // running c = m @ Wmh.T (red-accumulated)
__device__ unsigned g_cnt, g_gen;
__device__ unsigned cnt_c[8];     // per 128-col c tile: phase1 units done (16/step)
__device__ unsigned cnt_out[8];   // per 256-col out tile completion (step-ordered)
__device__ unsigned cnt_init[8];  // per 256-col out tile bm-init events

// ---------------- packed fp32x2 ----------------
__device__ __forceinline__ unsigned long long pack2(float a) {
    unsigned long long r;
    asm("mov.b64 %0, {%1, %1};" : "=l"(r) : "f"(a));
    return r;
}
__device__ __forceinline__ void ffma2(unsigned long long& c, unsigned long long a, unsigned long long b) {
    asm("fma.rn.f32x2 %0, %1, %2, %0;" : "+l"(c) : "l"(a), "l"(b));
}

// ---------------- L2-side vector reduction ----------------
__device__ __forceinline__ void red_add_v4(float* p, float4 v) {
    asm volatile("red.global.add.v4.f32 [%0], {%1,%2,%3,%4};"
                 :: "l"(p), "f"(v.x), "f"(v.y), "f"(v.z), "f"(v.w) : "memory");
}

// ---------------- sync primitives ----------------
__device__ __forceinline__ unsigned ldacq(const unsigned* p) {
    unsigned v;
    asm volatile("ld.acquire.gpu.global.u32 %0, [%1];" : "=r"(v) : "l"(p) : "memory");
    return v;
}
__device__ __forceinline__ void halfbar(int id) {
    asm volatile("bar.sync %0, %1;" :: "r"(id), "r"(256) : "memory");
}
__device__ __forceinline__ void grid_barrier() {
    __threadfence();
    __syncthreads();
    if (threadIdx.x == 0) {
        volatile unsigned* vg = &g_gen;
        unsigned old = *vg;
        unsigned prev = atomicAdd(&g_cnt, 1u);
        if (prev == NB - 1) {
            atomicExch(&g_cnt, 0u);
            __threadfence();
            atomicAdd(&g_gen, 1u);
        } else {
            while (*vg == old) { __nanosleep(64); }
        }
    }
    __syncthreads();
}

__device__ __forceinline__ int kval_d(int t) { return t ? min(__ffs(t), 8) : 8; }
// units = 2*k*sp3 <= 256; Kc = 3072/sp3 is a multiple of 16
__device__ __forceinline__ int sp3_of(int k) {
    return (k <= 2) ? 64 : (k <= 4) ? 32 : (k == 5) ? 24 : 16;
}

// ---------------- tile compute: 64 rows x 128 cols, 256 thr, 8x4 ----------
__device__ __forceinline__ void tile82(const float* As, const float* Bs,
                                       int ty, int tx, unsigned long long acc[8][2]) {
#pragma unroll
    for (int kk = 0; kk < 16; kk++) {
        float4 a0 = *(const float4*)(As + kk * AS_STR + ty * 8);
        float4 a1 = *(const float4*)(As + kk * AS_STR + ty * 8 + 4);
        const unsigned long long* bp = (const unsigned long long*)(Bs + kk * BS_STR + tx * 4);
        unsigned long long b0 = bp[0], b1 = bp[1];
        float as[8] = {a0.x, a0.y, a0.z, a0.w, a1.x, a1.y, a1.z, a1.w};
#pragma unroll
        for (int r = 0; r < 8; r++) {
            unsigned long long av = pack2(as[r]);
            ffma2(acc[r][0], av, b0);
            ffma2(acc[r][1], av, b1);
        }
    }
}
// ---------------- 64x256, 256 thr, 8x8 (prologue only) ----------
__device__ __forceinline__ void tile_compute8(const float* As, const float* Bs,
                                              int ty, int tx, unsigned long long acc[8][4]) {
#pragma unroll
    for (int kk = 0; kk < 16; kk++) {
        float4 a0 = *(const float4*)(As + kk * 68 + ty * 8);
        float4 a1 = *(const float4*)(As + kk * 68 + ty * 8 + 4);
        const unsigned long long* bp = (const unsigned long long*)(Bs + kk * 260 + tx * 8);
        unsigned long long b0 = bp[0], b1 = bp[1], b2 = bp[2], b3 = bp[3];
        float as[8] = {a0.x, a0.y, a0.z, a0.w, a1.x, a1.y, a1.z, a1.w};
#pragma unroll
        for (int r = 0; r < 8; r++) {
            unsigned long long av = pack2(as[r]);
            ffma2(acc[r][0], av, b0);
            ffma2(acc[r][1], av, b1);
            ffma2(acc[r][2], av, b2);
            ffma2(acc[r][3], av, b3);
        }
    }
}

// ---------------- prologue: g_xh = x @ Wxh + bh ----------------
__global__ __launch_bounds__(256) void xh_kernel(
    const float* __restrict__ X, const float* __restrict__ Wxh, const float* __restrict__ bh)
{
    __shared__ float As[16 * 68];
    __shared__ float Bs[16 * 260];
    const int tid = threadIdx.x;
    const int ty = tid >> 5, tx = tid & 31;
    const int colBase = blockIdx.x * 256;
    const int rowBase = blockIdx.y * 64;

    unsigned long long acc[8][4];
#pragma unroll
    for (int r = 0; r < 8; r++)
#pragma unroll
        for (int c = 0; c < 4; c++) acc[r][c] = 0ULL;

    for (int ch = 0; ch < 32; ch++) {
        int kb = ch << 4;
        {
            int row = tid >> 2, kl = (tid & 3) << 2;
            float4 v = *(const float4*)(X + (size_t)(rowBase + row) * IN_DIM + kb + kl);
            As[(kl + 0) * 68 + row] = v.x; As[(kl + 1) * 68 + row] = v.y;
            As[(kl + 2) * 68 + row] = v.z; As[(kl + 3) * 68 + row] = v.w;
        }
#pragma unroll
        for (int i = 0; i < 4; i++) {
            int g = tid + i * 256;
            int kl = g >> 6, col4 = (g & 63) << 2;
            float4 v = *(const float4*)(Wxh + (size_t)(kb + kl) * HID + colBase + col4);
            *(float4*)(Bs + kl * 260 + col4) = v;
        }
        __syncthreads();
        tile_compute8(As, Bs, ty, tx, acc);
        __syncthreads();
    }
#pragma unroll
    for (int r = 0; r < 8; r++) {
        int row = rowBase + ty * 8 + r;
        int jg = colBase + tx * 8;
#pragma unroll
        for (int c = 0; c < 4; c++) {
            float2 v = *(float2*)&acc[r][c];
            float2 bb = *(const float2*)(bh + jg + c * 2);
            v.x += bb.x; v.y += bb.y;
            *(float2*)(g_xh + (size_t)row * HID + jg + c * 2) = v;
        }
    }
}

// ======== phase-3 unit body (shared by both halves via macro) ========
// uses from scope: unit, t, kcur, sp3, mP, Wmm, Whm, out, eo, eI, lead,
// ty, tx, arow, akl
#define P3_LOADB(CH) do { int kb = kb0 + ((CH) << 4);                                      \
    { int jg = colBase + arow;                                                             \
      bR0 = (kb < MDIM) ? *(const float4*)(Wmm + (size_t)jg * MDIM + kb + akl)             \
                        : *(const float4*)(Whm + (size_t)jg * HID + (kb - MDIM) + akl); }  \
    { int jg = colBase + 64 + arow;                                                        \
      bR1 = (kb < MDIM) ? *(const float4*)(Wmm + (size_t)jg * MDIM + kb + akl)             \
                        : *(const float4*)(Whm + (size_t)jg * HID + (kb - MDIM) + akl); }  \
} while (0)

#define P3_LOADA(CH) do { int kb = kb0 + ((CH) << 4);                                      \
    if (kb < MDIM) {                                                                       \
        aR = __ldcg((const float4*)(mP + (size_t)arow * MDIM + kb + akl));                 \
    } else {                                                                               \
        size_t hoff = (size_t)arow * HID + (kb - MDIM) + akl;                              \
        float4 cc = __ldcg((const float4*)(g_c + hoff));                                   \
        float4 xx = *(const float4*)(g_xh + (size_t)t * BH + hoff);                        \
        aR = make_float4(tanhf(xx.x + cc.x), tanhf(xx.y + cc.y),                           \
                         tanhf(xx.z + cc.z), tanhf(xx.w + cc.w));                          \
    }                                                                                      \
} while (0)

#define PX_STORE(AP, BP, BF) do { float* A_ = (AP) + (BF) * AS_SZ; float* B_ = (BP) + (BF) * BS_SZ; \
    A_[(akl + 0) * AS_STR + arow] = aR.x; A_[(akl + 1) * AS_STR + arow] = aR.y;            \
    A_[(akl + 2) * AS_STR + arow] = aR.z; A_[(akl + 3) * AS_STR + arow] = aR.w;            \
    B_[(akl + 0) * BS_STR + arow] = bR0.x; B_[(akl + 1) * BS_STR + arow] = bR0.y;          \
    B_[(akl + 2) * BS_STR + arow] = bR0.z; B_[(akl + 3) * BS_STR + arow] = bR0.w;          \
    B_[(akl + 0) * BS_STR + 64 + arow] = bR1.x; B_[(akl + 1) * BS_STR + 64 + arow] = bR1.y;\
    B_[(akl + 2) * BS_STR + 64 + arow] = bR1.z; B_[(akl + 3) * BS_STR + 64 + arow] = bR1.w;\
} while (0)

#define PHASE3_BODY(AP, BP, BARID)                                                         \
{                                                                                          \
    const int Kc3 = 3072 / sp3;                                                            \
    const int chunks = Kc3 >> 4;                                                           \
    const int t128 = unit / sp3;                                                           \
    const int s = unit - t128 * sp3;                                                       \
    const int colBase = t128 * 128;                                                        \
    const int ct256 = t128 >> 1;                                                           \
    const int kb0 = s * Kc3;                                                               \
    const int kend = kb0 + Kc3;                                                            \
    const int hstart = (kb0 >= MDIM) ? 0 : ((kend <= MDIM) ? chunks : ((MDIM - kb0) >> 4));\
    float4 aR = make_float4(0.f,0.f,0.f,0.f);                                              \
    float4 bR0, bR1;                                                                       \
    P3_LOADB(0);   /* weight prefetch overlaps the waits */                                \
    if (lead) {                                                                            \
        while (ldacq(&cnt_init[ct256]) < (unsigned)eI[ct256]) { }                          \
        const int mk1 = min(kend, MDIM);                                                   \
        if (t && mk1 > kb0) {                                                              \
            const int jlo = kb0 >> 8, jhi = (mk1 - 1) >> 8;                                \
            for (int j = jlo; j <= jhi; j++)                                               \
                while (ldacq(&cnt_out[j]) < (unsigned)eo[j]) { }                           \
        }                                                                                  \
        if (hstart == 0) {                                                                 \
            const int jlo = (kb0 - MDIM) >> 7, jhi = (kend - 1 - MDIM) >> 7;               \
            for (int j = jlo; j <= jhi; j++)                                               \
                while (ldacq(&cnt_c[j]) < 16u * (unsigned)(t + 1)) { }                     \
        }                                                                                  \
    }                                                                                      \
    halfbar(BARID);                                                                        \
    unsigned long long acc[8][2];                                                          \
    _Pragma("unroll")                                                                      \
    for (int r = 0; r < 8; r++) { acc[r][0] = 0ULL; acc[r][1] = 0ULL; }                    \
    P3_LOADA(0); PX_STORE(AP, BP, 0); halfbar(BARID);                                      \
    for (int ch = 0; ch < chunks; ch++) {                                                  \
        if (ch + 1 < chunks) {                                                             \
            if (ch + 1 == hstart) {                                                        \
                if (lead) {                                                                \
                    const int jhi2 = (kend - 1 - MDIM) >> 7;                               \
                    for (int j = 0; j <= jhi2; j++)                                        \
                        while (ldacq(&cnt_c[j]) < 16u * (unsigned)(t + 1)) { }             \
                }                                                                          \
                halfbar(BARID);                                                            \
            }                                                                              \
            P3_LOADB(ch + 1); P3_LOADA(ch + 1);                                            \
        }                                                                                  \
        tile82((AP) + (ch & 1) * AS_SZ, (BP) + (ch & 1) * BS_SZ, ty, tx, acc);             \
        if (ch + 1 < chunks) { PX_STORE(AP, BP, (ch + 1) & 1); halfbar(BARID); }           \
    }                                                                                      \
    {                                                                                      \
        float* obase = out + (size_t)t * BM;                                               \
        _Pragma("unroll")                                                                  \
        for (int r = 0; r < 8; r++) {                                                      \
            float2 a0 = *(float2*)&acc[r][0], a1 = *(float2*)&acc[r][1];                   \
            red_add_v4(obase + (size_t)(ty * 8 + r) * MDIM + colBase + tx * 4,             \
                       make_float4(a0.x, a0.y, a1.x, a1.y));                               \
        }                                                                                  \
    }                                                                                      \
    /* step-ordering poll + fence + single bar + signal */                                 \
    if (lead) { while (ldacq(&cnt_out[ct256]) < (unsigned)eo[ct256]) { } }                 \
    __threadfence();                                                                       \
    halfbar(BARID);                                                                        \
    if (lead) atomicAdd(&cnt_out[ct256], 1u);                                              \
}

// ---------------- persistent dataflow recurrence (warp-specialized halves) ----
__global__ __launch_bounds__(NTF, 1) void rnn_persistent(
    const float* __restrict__ m_prev, const float* __restrict__ Wmh,
    const float* __restrict__ Wmm, const float* __restrict__ Whm,
    const float* __restrict__ bm, float* __restrict__ out)
{
    extern __shared__ float sm[];
    float* AsA = sm;
    float* BsA = sm + 2 * AS_SZ;
    float* AsB = sm + 2 * AS_SZ + 2 * BS_SZ;
    float* BsB = AsB + 2 * AS_SZ;

    const int tid = threadIdx.x;
    const int bid = blockIdx.x;

    // ---- startup (full block): reset counters, zero g_c, out[0]=bm ----
    if (bid == 0 && tid == 0) {
#pragma unroll
        for (int i = 0; i < 8; i++) { cnt_c[i] = 0; cnt_out[i] = 0; cnt_init[i] = 0; }
    }
    {
        int ft = bid * NTF + tid;          // [0, 65536)
        g_c[ft] = 0.0f;
        int col = (ft * 2) & (MDIM - 1);
        *(float2*)(out + (size_t)ft * 2) = *(const float2*)(bm + col);
    }
    grid_barrier();

    if (tid < 256) {
        // ============ HALF A: phase1 + bm-init + copies + phase3 overflow ============
        const int l = tid;
        const bool lead = (l == 0);
        const int ty = l >> 5, tx = l & 31;
        const int arow = l >> 2, akl = (l & 3) << 2;
        int eo[8], eI[8];
#pragma unroll
        for (int j = 0; j < 8; j++) { eo[j] = 0; eI[j] = 0; }

        for (int t = 0; t < T_STEPS; t++) {
            const float* mP  = t ? (out + (size_t)(t - 1) * BM) : m_prev;
            const float* mPP = (t >= 2) ? (out + (size_t)(t - 2) * BM) : m_prev;
            const int kcur  = kval_d(t);
            const int kprev = (t <= 1) ? 8 : kval_d(t - 1);
            const int sp3   = sp3_of(kcur);
            const int units = 2 * kcur * sp3;

            // ---- phase1: red(dm @ Wmh.T) into g_c ----
            {
                const int ct4 = bid >> 4, s = bid & 15;
                const int kb0 = s * (kprev << 4);
                const int colBase = ct4 * 128;
                float4 aR = make_float4(0.f,0.f,0.f,0.f);
                float4 bR0, bR1;
                // prefetch weights chunk 0 before the waits
                bR0 = *(const float4*)(Wmh + (size_t)(colBase + arow) * MDIM + kb0 + akl);
                bR1 = *(const float4*)(Wmh + (size_t)(colBase + 64 + arow) * MDIM + kb0 + akl);
                if (t && lead) {
                    for (int j = 0; j < kprev; j++)
                        while (ldacq(&cnt_out[j]) < (unsigned)eo[j]) { }
                }
                halfbar(1);
                unsigned long long acc[8][2];
#pragma unroll
                for (int r = 0; r < 8; r++) { acc[r][0] = 0ULL; acc[r][1] = 0ULL; }

#define P1_LOADA(CH) do { int kb = kb0 + ((CH) << 4);                                      \
    if (t) {                                                                               \
        float4 p = __ldcg((const float4*)(mP  + (size_t)arow * MDIM + kb + akl));          \
        float4 q = __ldcg((const float4*)(mPP + (size_t)arow * MDIM + kb + akl));          \
        aR = make_float4(p.x - q.x, p.y - q.y, p.z - q.z, p.w - q.w);                      \
    } else {                                                                               \
        aR = *(const float4*)(m_prev + (size_t)arow * MDIM + kb + akl);                    \
    }                                                                                      \
} while (0)
#define P1_LOADB(CH) do { int kb = kb0 + ((CH) << 4);                                      \
    bR0 = *(const float4*)(Wmh + (size_t)(colBase + arow) * MDIM + kb + akl);              \
    bR1 = *(const float4*)(Wmh + (size_t)(colBase + 64 + arow) * MDIM + kb + akl);         \
} while (0)

                P1_LOADA(0); PX_STORE(AsA, BsA, 0); halfbar(1);
                for (int ch = 0; ch < kprev; ch++) {
                    if (ch + 1 < kprev) { P1_LOADB(ch + 1); P1_LOADA(ch + 1); }
                    tile82(AsA + (ch & 1) * AS_SZ, BsA + (ch & 1) * BS_SZ, ty, tx, acc);
                    if (ch + 1 < kprev) { PX_STORE(AsA, BsA, (ch + 1) & 1); halfbar(1); }
                }
#pragma unroll
                for (int r = 0; r < 8; r++) {
                    float2 a0 = *(float2*)&acc[r][0], a1 = *(float2*)&acc[r][1];
                    red_add_v4(g_c + (size_t)(ty * 8 + r) * HID + colBase + tx * 4,
                               make_float4(a0.x, a0.y, a1.x, a1.y));
                }
                __threadfence();
                halfbar(1);
                if (lead) atomicAdd(&cnt_c[ct4], 1u);
            }

            // ---- bm-init out[t+1] active tiles ----
            if (t + 1 < T_STEPS) {
                int kn = kval_d(t + 1);
                int j = bid - 120;
                if (j >= 0 && j < kn) {
                    float* dst = out + (size_t)(t + 1) * BM;
                    for (int idx = l; idx < 4096; idx += 256) {
                        int row = idx >> 6, c4 = (idx & 63) << 2;
                        *(float4*)(dst + (size_t)row * MDIM + j * 256 + c4) =
                            *(const float4*)(bm + j * 256 + c4);
                    }
                    __threadfence();
                    halfbar(1);
                    if (lead) atomicAdd(&cnt_init[j], 1u);
                }
            }

            // ---- copies: inactive tiles (wait = RAW + signal ordering) ----
            {
                const int ct8 = bid >> 4, part = bid & 15;
                if (ct8 >= kcur) {
                    if (lead) { while (ldacq(&cnt_out[ct8]) < (unsigned)eo[ct8]) { } }
                    halfbar(1);
                    int row = l >> 2;
                    int col = ct8 * 256 + part * 16 + (l & 3) * 4;
                    size_t moff = (size_t)row * MDIM + col;
                    float4 v = __ldcg((const float4*)(mP + moff));
                    *(float4*)(out + (size_t)t * BM + moff) = v;
                    __threadfence();
                    halfbar(1);
                    if (lead) atomicAdd(&cnt_out[ct8], 1u);
                }
            }

            // ---- phase3 overflow units ----
            if (128 + bid < units) {
                const int unit = 128 + bid;
                PHASE3_BODY(AsA, BsA, 1);
            }

            // ---- bookkeeping ----
            {
                const int as = 2 * sp3;
#pragma unroll
                for (int j = 0; j < 8; j++) eo[j] += (j < kcur) ? as : 16;
                if (t + 1 < T_STEPS) {
                    int kn = kval_d(t + 1);
#pragma unroll
                    for (int j = 0; j < 8; j++) if (j < kn) eI[j]++;
                }
            }
        }

        // ---- final: m_T = out[255] ----
        if (lead) {
#pragma unroll
            for (int j = 0; j < 8; j++)
                while (ldacq(&cnt_out[j]) < (unsigned)eo[j]) { }
        }
        halfbar(1);
        {
            int ft2 = bid * 256 + l;      // [0, 32768)
            float4 v = __ldcg((const float4*)(out + (size_t)(T_STEPS - 1) * BM + (size_t)ft2 * 4));
            *(float4*)(out + (size_t)T_STEPS * BM + (size_t)ft2 * 4) = v;
        }
    } else {
        // ============ HALF B: phase3 main units ============
        const int l = tid - 256;
        const bool lead = (l == 0);
        const int ty = l >> 5, tx = l & 31;
        const int arow = l >> 2, akl = (l & 3) << 2;
        int eo[8], eI[8];
#pragma unroll
        for (int j = 0; j < 8; j++) { eo[j] = 0; eI[j] = 0; }

        for (int t = 0; t < T_STEPS; t++) {
            const float* mP = t ? (out + (size_t)(t - 1) * BM) : m_prev;
            const int kcur = kval_d(t);
            const int sp3 = sp3_of(kcur);
            const int units = 2 * kcur * sp3;
            if (bid < units) {      // always true (units >= 128), kept for safety
                const int unit = bid;
                PHASE3_BODY(AsB, BsB, 2);
            }
            // ---- bookkeeping ----
            {
                const int as = 2 * sp3;
#pragma unroll
                for (int j = 0; j < 8; j++) eo[j] += (j < kcur) ? as : 16;
                if (t + 1 < T_STEPS) {
                    int kn = kval_d(t + 1);
#pragma unroll
                    for (int j = 0; j < 8; j++) if (j < kn) eI[j]++;
                }
            }
        }
    }
}

// ---------------- host ----------------
extern "C" void kernel_launch(void* const* d_in, const int* in_sizes, int n_in,
                              void* d_out, int out_size)
{
    const float* x      = (const float*)d_in[0];
    const float* m_prev = (const float*)d_in[1];
    const float* Wxh    = (const float*)d_in[2];
    const float* Whm    = (const float*)d_in[3];
    const float* Wmm    = (const float*)d_in[4];
    const float* Wmh    = (const float*)d_in[5];
    const float* bm     = (const float*)d_in[6];
    const float* bh     = (const float*)d_in[7];
    float* out = (float*)d_out;
    (void)in_sizes; (void)n_in; (void)out_size;

    cudaFuncSetAttribute(rnn_persistent,
                         cudaFuncAttributeMaxDynamicSharedMemorySize,
                         SMEM_FLOATS * sizeof(float));

    xh_kernel<<<dim3(4, 256), 256>>>(x, Wxh, bh);
    rnn_persistent<<<NB, NTF, SMEM_FLOATS * sizeof(float)>>>(m_prev, Wmh, Wmm, Whm, bm, out);
}